// round 13
// baseline (speedup 1.0000x reference)
#include <cuda_runtime.h>
#include <cuda_fp16.h>
#include <math.h>

#define N_NODES 100000
#define N_EDGES 1600000
#define NUSER   90000
#define NT2     (2 * NUSER)            // merged bucket count = 180000
#define SCAN_CHUNK 1024
#define NPART   ((NT2 + SCAN_CHUNK - 1) / SCAN_CHUNK)   // 176

// ---------------- scratch (device globals; no allocation allowed) ----------
__device__ __align__(16) __half g_hp0[N_NODES * 128];
__device__ __align__(16) __half g_hp1[N_NODES * 128];
__device__ __align__(16) float g_as [2 * N_NODES * 2];  // [layer][n*2+h]
__device__ __align__(16) float g_at [2 * N_NODES * 2];
__device__ __align__(16) float g_ta [NUSER  * 128];     // type_aware (n, k, d)
__device__ __align__(16) float g_u  [NUSER  * 64];
__device__ __align__(16) float g_v  [NUSER  * 128];
__device__ __align__(16) int   g_cnt[NT2];              // counts
__device__ __align__(16) int   g_off[NT2];              // CSR offsets
__device__ __align__(16) int   g_cur[NT2];              // scatter cursors
__device__ __align__(16) int   g_part[256];
__device__ __align__(16) int   g_csr[2 * N_EDGES];      // bucketed src ids

// ---------------- fused hp GEMM + attn logits -------------------------------
__global__ __launch_bounds__(256)
void gemm_hp_fused(const float* __restrict__ A,
                   const float* __restrict__ W0, const float* __restrict__ W1,
                   const float* __restrict__ asrc0, const float* __restrict__ atrg0,
                   const float* __restrict__ asrc1, const float* __restrict__ atrg1,
                   __half* __restrict__ hp0, __half* __restrict__ hp1,
                   float* __restrict__ asOut, float* __restrict__ atOut, int M)
{
    constexpr int P   = 128;
    constexpr int BM  = 128;
    constexpr int LDA = BM + 4;

    const int layer = blockIdx.y;
    const float* Braw = layer ? W1 : W0;
    const float* aS   = layer ? asrc1 : asrc0;
    const float* aT   = layer ? atrg1 : atrg0;
    __half* hpL = layer ? hp1 : hp0;

    extern __shared__ float smem[];
    float* As = smem;                        // [64][LDA]
    float* Bs = smem + 64 * LDA;             // [64][128]

    const int t    = threadIdx.x;
    const int row0 = blockIdx.x * BM;

    #pragma unroll 4
    for (int i = t; i < 64 * P; i += 256) {
        int kk = i >> 7, c = i & 127;
        Bs[kk * P + c] = Braw[(c >> 6) * 4096 + kk * 64 + (c & 63)];
    }
    #pragma unroll 4
    for (int i = t; i < BM * 16; i += 256) {
        int r  = i >> 4;
        int k4 = (i & 15) << 2;
        float4 a = make_float4(0.f, 0.f, 0.f, 0.f);
        if (row0 + r < M) a = *(const float4*)(A + (size_t)(row0 + r) * 64 + k4);
        As[(k4 + 0) * LDA + r] = a.x;
        As[(k4 + 1) * LDA + r] = a.y;
        As[(k4 + 2) * LDA + r] = a.z;
        As[(k4 + 3) * LDA + r] = a.w;
    }
    __syncthreads();

    const int cg = t & 15;
    const int rg = t >> 4;

    float acc[8][8];
    #pragma unroll
    for (int r = 0; r < 8; r++)
        #pragma unroll
        for (int c = 0; c < 8; c++) acc[r][c] = 0.f;

    #pragma unroll
    for (int k = 0; k < 64; k++) {
        float4 a0 = *(const float4*)(As + k * LDA + rg * 8);
        float4 a1 = *(const float4*)(As + k * LDA + rg * 8 + 4);
        float a[8] = {a0.x, a0.y, a0.z, a0.w, a1.x, a1.y, a1.z, a1.w};
        float4 b0 = *(const float4*)(Bs + k * P + cg * 8);
        float4 b1 = *(const float4*)(Bs + k * P + cg * 8 + 4);
        float b[8] = {b0.x, b0.y, b0.z, b0.w, b1.x, b1.y, b1.z, b1.w};
        #pragma unroll
        for (int r = 0; r < 8; r++)
            #pragma unroll
            for (int c = 0; c < 8; c++)
                acc[r][c] = fmaf(a[r], b[c], acc[r][c]);
    }

    #pragma unroll
    for (int r = 0; r < 8; r++) {
        int row = row0 + rg * 8 + r;
        if (row < M) {
            union { __half2 h2[4]; uint4 u4; } pk;
            #pragma unroll
            for (int c2 = 0; c2 < 4; c2++)
                pk.h2[c2] = __floats2half2_rn(acc[r][2*c2], acc[r][2*c2+1]);
            *(uint4*)(hpL + (size_t)row * 128 + cg * 8) = pk.u4;
        }
    }

    float4 s0 = *(const float4*)(aS + cg * 8);
    float4 s1 = *(const float4*)(aS + cg * 8 + 4);
    float4 t0 = *(const float4*)(aT + cg * 8);
    float4 t1 = *(const float4*)(aT + cg * 8 + 4);
    float sv[8] = {s0.x, s0.y, s0.z, s0.w, s1.x, s1.y, s1.z, s1.w};
    float tv[8] = {t0.x, t0.y, t0.z, t0.w, t1.x, t1.y, t1.z, t1.w};

    float pas[8], pat[8];
    #pragma unroll
    for (int r = 0; r < 8; r++) {
        float a_ = 0.f, b_ = 0.f;
        #pragma unroll
        for (int c = 0; c < 8; c++) {
            a_ = fmaf(acc[r][c], sv[c], a_);
            b_ = fmaf(acc[r][c], tv[c], b_);
        }
        pas[r] = a_; pat[r] = b_;
    }
    #pragma unroll
    for (int o = 1; o < 8; o <<= 1) {
        #pragma unroll
        for (int r = 0; r < 8; r++) {
            pas[r] += __shfl_xor_sync(0xffffffffu, pas[r], o);
            pat[r] += __shfl_xor_sync(0xffffffffu, pat[r], o);
        }
    }
    if ((cg & 7) == 0) {
        int head  = cg >> 3;
        int abase = layer * N_NODES * 2;
        #pragma unroll
        for (int r = 0; r < 8; r++) {
            int row = row0 + rg * 8 + r;
            if (row < M) {
                asOut[abase + row * 2 + head] = pas[r];
                atOut[abase + row * 2 + head] = pat[r];
            }
        }
    }
}

// ---------------- head GEMMs merged: y=0 -> u = h@aaw1^T ; y=1 -> v = ta@aaw2^T
__global__ __launch_bounds__(256)
void gemm_head(const float* __restrict__ A0, const float* __restrict__ B0,
               float* __restrict__ C0, int M0,
               const float* __restrict__ A1, const float* __restrict__ B1,
               float* __restrict__ C1, int M1)
{
    constexpr int P   = 64;
    constexpr int BM  = 128;
    constexpr int LDA = BM + 4;

    const int sel = blockIdx.y;
    const float* A    = sel ? A1 : A0;
    const float* Braw = sel ? B1 : B0;
    float*       C    = sel ? C1 : C0;
    const int    M    = sel ? M1 : M0;

    const int row0 = blockIdx.x * BM;
    if (row0 >= M) return;

    extern __shared__ float smem[];
    float* As = smem;
    float* Bs = smem + 64 * LDA;

    const int t = threadIdx.x;

    #pragma unroll 4
    for (int i = t; i < 64 * P; i += 256) {
        int kk = i / P, c = i % P;
        Bs[kk * P + c] = Braw[c * 64 + kk];
    }
    #pragma unroll 4
    for (int i = t; i < BM * 16; i += 256) {
        int r  = i >> 4;
        int k4 = (i & 15) << 2;
        float4 a = make_float4(0.f, 0.f, 0.f, 0.f);
        if (row0 + r < M) a = *(const float4*)(A + (size_t)(row0 + r) * 64 + k4);
        As[(k4 + 0) * LDA + r] = a.x;
        As[(k4 + 1) * LDA + r] = a.y;
        As[(k4 + 2) * LDA + r] = a.z;
        As[(k4 + 3) * LDA + r] = a.w;
    }
    __syncthreads();

    const int cg = t & 15;
    const int rg = t >> 4;

    float acc[8][4];
    #pragma unroll
    for (int r = 0; r < 8; r++)
        #pragma unroll
        for (int c = 0; c < 4; c++) acc[r][c] = 0.f;

    #pragma unroll
    for (int k = 0; k < 64; k++) {
        float4 a0 = *(const float4*)(As + k * LDA + rg * 8);
        float4 a1 = *(const float4*)(As + k * LDA + rg * 8 + 4);
        float a[8] = {a0.x, a0.y, a0.z, a0.w, a1.x, a1.y, a1.z, a1.w};
        float4 b0 = *(const float4*)(Bs + k * P + cg * 4);
        float b[4] = {b0.x, b0.y, b0.z, b0.w};
        #pragma unroll
        for (int r = 0; r < 8; r++)
            #pragma unroll
            for (int c = 0; c < 4; c++)
                acc[r][c] = fmaf(a[r], b[c], acc[r][c]);
    }

    #pragma unroll
    for (int r = 0; r < 8; r++) {
        int row = row0 + rg * 8 + r;
        if (row < M) {
            float4 o = make_float4(acc[r][0], acc[r][1], acc[r][2], acc[r][3]);
            *(float4*)(C + (size_t)row * P + cg * 4) = o;
        }
    }
}

// ---------------- CSR build --------------------------------------------------
__global__ void zero_cnt_kernel(int* __restrict__ cnt)
{
    int i = blockIdx.x * blockDim.x + threadIdx.x;
    if (i < NT2) cnt[i] = 0;
}

// 4 edges per thread: 4 independent atomic chains in flight
__global__ __launch_bounds__(256)
void hist_kernel(const int* __restrict__ trgA, const int* __restrict__ trgB,
                 int* __restrict__ cnt)
{
    int i4 = blockIdx.x * blockDim.x + threadIdx.x;
    if (i4 >= 2 * (N_EDGES / 4)) return;
    int layer = (i4 >= N_EDGES / 4);
    const int* trg = layer ? trgB : trgA;
    int e4 = i4 - layer * (N_EDGES / 4);
    int4 t4 = __ldg((const int4*)trg + e4);
    int base = layer * NUSER;
    if (t4.x < NUSER) atomicAdd(cnt + base + t4.x, 1);
    if (t4.y < NUSER) atomicAdd(cnt + base + t4.y, 1);
    if (t4.z < NUSER) atomicAdd(cnt + base + t4.z, 1);
    if (t4.w < NUSER) atomicAdd(cnt + base + t4.w, 1);
}

__global__ __launch_bounds__(256)
void scan1_kernel(const int* __restrict__ cnt, int* __restrict__ off,
                  int* __restrict__ part)
{
    __shared__ int s[256];
    int t = threadIdx.x, b = blockIdx.x;
    int i0 = b * SCAN_CHUNK + t * 4;
    int c[4];
    #pragma unroll
    for (int j = 0; j < 4; j++) c[j] = (i0 + j < NT2) ? cnt[i0 + j] : 0;
    int tot = c[0] + c[1] + c[2] + c[3];
    s[t] = tot;
    __syncthreads();
    int v = s[t];
    #pragma unroll
    for (int o = 1; o < 256; o <<= 1) {
        int u = (t >= o) ? s[t - o] : 0;
        __syncthreads();
        v += u; s[t] = v;
        __syncthreads();
    }
    int excl = v - tot;
    #pragma unroll
    for (int j = 0; j < 4; j++) {
        if (i0 + j < NT2) off[i0 + j] = excl;
        excl += c[j];
    }
    if (t == 255) part[b] = v;
}

__global__ void scan2_kernel(int* __restrict__ part)
{
    __shared__ int s[256];
    int t = threadIdx.x;
    int own = (t < NPART) ? part[t] : 0;
    s[t] = own;
    __syncthreads();
    int v = s[t];
    #pragma unroll
    for (int o = 1; o < 256; o <<= 1) {
        int u = (t >= o) ? s[t - o] : 0;
        __syncthreads();
        v += u; s[t] = v;
        __syncthreads();
    }
    if (t < NPART) part[t] = v - own;
}

// add chunk base AND initialize scatter cursor
__global__ void scan3_kernel(int* __restrict__ off, const int* __restrict__ part,
                             int* __restrict__ cur)
{
    int i = blockIdx.x * blockDim.x + threadIdx.x;
    if (i < NT2) {
        int o = off[i] + part[i / SCAN_CHUNK];
        off[i] = o;
        cur[i] = o;
    }
}

// 4 edges per thread: 4 independent atomic-return chains in flight
__global__ __launch_bounds__(256)
void scatter_kernel(const int* __restrict__ srcA, const int* __restrict__ trgA,
                    const int* __restrict__ srcB, const int* __restrict__ trgB,
                    int* __restrict__ cur, int* __restrict__ csr)
{
    int i4 = blockIdx.x * blockDim.x + threadIdx.x;
    if (i4 >= 2 * (N_EDGES / 4)) return;
    int layer = (i4 >= N_EDGES / 4);
    int e4 = i4 - layer * (N_EDGES / 4);
    const int* trg = layer ? trgB : trgA;
    const int* src = layer ? srcB : srcA;
    int4 t4 = __ldg((const int4*)trg + e4);
    int4 s4 = __ldg((const int4*)src + e4);
    int base = layer * NUSER;
    int p0 = (t4.x < NUSER) ? atomicAdd(cur + base + t4.x, 1) : -1;
    int p1 = (t4.y < NUSER) ? atomicAdd(cur + base + t4.y, 1) : -1;
    int p2 = (t4.z < NUSER) ? atomicAdd(cur + base + t4.z, 1) : -1;
    int p3 = (t4.w < NUSER) ? atomicAdd(cur + base + t4.w, 1) : -1;
    if (p0 >= 0) csr[p0] = s4.x;
    if (p1 >= 0) csr[p1] = s4.y;
    if (p2 >= 0) csr[p2] = s4.z;
    if (p3 >= 0) csr[p3] = s4.w;
}

// ---------------- gather: warp per (layer, target), unrolled x2 (R11) -------
__global__ __launch_bounds__(256)
void gather_kernel(const int* __restrict__ csr, const int* __restrict__ off,
                   const int* __restrict__ cnt,
                   const float* __restrict__ as_, const float* __restrict__ at_,
                   const __half* __restrict__ hp0, const __half* __restrict__ hp1,
                   float* __restrict__ ta)
{
    int w    = (blockIdx.x * blockDim.x + threadIdx.x) >> 5;
    int lane = threadIdx.x & 31;
    if (w >= NT2) return;
    int layer = (w >= NUSER);
    int t = w - layer * NUSER;
    const __half* hpL = layer ? hp1 : hp0;
    int abase = layer * N_NODES * 2;

    int grp  = lane >> 4;        // which edge of the pair
    int sub  = lane & 15;        // 16-lane slot within edge
    int hsel = sub >> 3;         // head of this lane

    float at_own = __ldg(at_ + abase + 2 * t + hsel);
    int start = __ldg(off + w);
    int n     = __ldg(cnt + w);

    float acc[8];
    #pragma unroll
    for (int j = 0; j < 8; j++) acc[j] = 0.f;
    float den = 0.f;

    int i = 0;
    // main loop: both chains unconditionally valid
    for (; i + 4 <= n; i += 4) {
        int sA = __ldg(csr + start + i + grp);
        int sB = __ldg(csr + start + i + 2 + grp);
        float eA = __ldg(as_ + abase + 2 * sA + hsel) + at_own;
        float eB = __ldg(as_ + abase + 2 * sB + hsel) + at_own;
        eA = (eA > 0.f) ? eA : 0.2f * eA;
        eB = (eB > 0.f) ? eB : 0.2f * eB;
        float wA = __expf(eA);
        float wB = __expf(eB);
        uint4 rA = *(const uint4*)(hpL + (size_t)sA * 128 + sub * 8);
        uint4 rB = *(const uint4*)(hpL + (size_t)sB * 128 + sub * 8);
        den += wA + wB;
        float2 f;
        f = __half22float2(*reinterpret_cast<__half2*>(&rA.x));
        acc[0] = fmaf(wA, f.x, acc[0]); acc[1] = fmaf(wA, f.y, acc[1]);
        f = __half22float2(*reinterpret_cast<__half2*>(&rA.y));
        acc[2] = fmaf(wA, f.x, acc[2]); acc[3] = fmaf(wA, f.y, acc[3]);
        f = __half22float2(*reinterpret_cast<__half2*>(&rA.z));
        acc[4] = fmaf(wA, f.x, acc[4]); acc[5] = fmaf(wA, f.y, acc[5]);
        f = __half22float2(*reinterpret_cast<__half2*>(&rA.w));
        acc[6] = fmaf(wA, f.x, acc[6]); acc[7] = fmaf(wA, f.y, acc[7]);
        f = __half22float2(*reinterpret_cast<__half2*>(&rB.x));
        acc[0] = fmaf(wB, f.x, acc[0]); acc[1] = fmaf(wB, f.y, acc[1]);
        f = __half22float2(*reinterpret_cast<__half2*>(&rB.y));
        acc[2] = fmaf(wB, f.x, acc[2]); acc[3] = fmaf(wB, f.y, acc[3]);
        f = __half22float2(*reinterpret_cast<__half2*>(&rB.z));
        acc[4] = fmaf(wB, f.x, acc[4]); acc[5] = fmaf(wB, f.y, acc[5]);
        f = __half22float2(*reinterpret_cast<__half2*>(&rB.w));
        acc[6] = fmaf(wB, f.x, acc[6]); acc[7] = fmaf(wB, f.y, acc[7]);
    }
    // tail: 2 edges per iteration with validity predicate
    for (; i < n; i += 2) {
        int idx = i + grp;
        bool valid = idx < n;
        int sidx = valid ? idx : i;
        int s = __ldg(csr + start + sidx);
        float e = __ldg(as_ + abase + 2 * s + hsel) + at_own;
        e = (e > 0.f) ? e : 0.2f * e;
        float wgt = valid ? __expf(e) : 0.f;
        den += wgt;
        uint4 r = *(const uint4*)(hpL + (size_t)s * 128 + sub * 8);
        float2 f;
        f = __half22float2(*reinterpret_cast<__half2*>(&r.x));
        acc[0] = fmaf(wgt, f.x, acc[0]); acc[1] = fmaf(wgt, f.y, acc[1]);
        f = __half22float2(*reinterpret_cast<__half2*>(&r.y));
        acc[2] = fmaf(wgt, f.x, acc[2]); acc[3] = fmaf(wgt, f.y, acc[3]);
        f = __half22float2(*reinterpret_cast<__half2*>(&r.z));
        acc[4] = fmaf(wgt, f.x, acc[4]); acc[5] = fmaf(wgt, f.y, acc[5]);
        f = __half22float2(*reinterpret_cast<__half2*>(&r.w));
        acc[6] = fmaf(wgt, f.x, acc[6]); acc[7] = fmaf(wgt, f.y, acc[7]);
    }

    den += __shfl_xor_sync(0xffffffffu, den, 16);
    #pragma unroll
    for (int j = 0; j < 8; j++)
        acc[j] += __shfl_xor_sync(0xffffffffu, acc[j], 16);

    float inv = 1.f / (den + 1e-16f);
    #pragma unroll
    for (int j = 0; j < 8; j++) acc[j] *= inv;

    float other[8];
    #pragma unroll
    for (int j = 0; j < 8; j++)
        other[j] = __shfl_xor_sync(0xffffffffu, acc[j], 8);

    if (grp == 0 && hsel == 0) {
        float4 r0 = make_float4(0.5f * (acc[0] + other[0]), 0.5f * (acc[1] + other[1]),
                                0.5f * (acc[2] + other[2]), 0.5f * (acc[3] + other[3]));
        float4 r1 = make_float4(0.5f * (acc[4] + other[4]), 0.5f * (acc[5] + other[5]),
                                0.5f * (acc[6] + other[6]), 0.5f * (acc[7] + other[7]));
        float* dst = ta + (size_t)t * 128 + layer * 64 + sub * 8;
        *(float4*)(dst)     = r0;
        *(float4*)(dst + 4) = r1;
    }
}

// ---------------- head: tanh-attention fusion + FC + log_softmax ------------
__global__ __launch_bounds__(256)
void head_kernel(const float* __restrict__ u, const float* __restrict__ v,
                 const float* __restrict__ ta,
                 const float* __restrict__ aam, const float* __restrict__ fcw,
                 const float* __restrict__ fcb, float* __restrict__ outp)
{
    int w    = (blockIdx.x * blockDim.x + threadIdx.x) >> 5;
    int lane = threadIdx.x & 31;
    if (w >= NUSER) return;
    int d1 = lane, d2 = lane + 32;

    float u1   = u[w * 64 + d1],            u2   = u[w * 64 + d2];
    float v01  = v[(2*w) * 64 + d1],        v02  = v[(2*w) * 64 + d2];
    float v11  = v[(2*w+1) * 64 + d1],      v12  = v[(2*w+1) * 64 + d2];
    float ta01 = ta[w * 128 + d1],          ta02 = ta[w * 128 + d2];
    float ta11 = ta[w * 128 + 64 + d1],     ta12 = ta[w * 128 + 64 + d2];
    float am1  = __ldg(aam + d1),           am2  = __ldg(aam + d2);

    float s0 = tanhf(u1 + v01) * am1 + tanhf(u2 + v02) * am2;
    float s1 = tanhf(u1 + v11) * am1 + tanhf(u2 + v12) * am2;
    #pragma unroll
    for (int o = 16; o > 0; o >>= 1) {
        s0 += __shfl_xor_sync(0xffffffffu, s0, o);
        s1 += __shfl_xor_sync(0xffffffffu, s1, o);
    }
    float m  = fmaxf(s0, s1);
    float e0 = expf(s0 - m), e1 = expf(s1 - m);
    float rb = 1.f / (e0 + e1);
    float b0 = e0 * rb, b1 = e1 * rb;

    float f1 = b0 * ta01 + b1 * ta11;
    float f2 = b0 * ta02 + b1 * ta12;

    float l0 = ta01 * __ldg(fcw + d1)        + ta02 * __ldg(fcw + d2)
             + ta11 * __ldg(fcw + 64 + d1)   + ta12 * __ldg(fcw + 64 + d2)
             + f1   * __ldg(fcw + 128 + d1)  + f2   * __ldg(fcw + 128 + d2);
    float l1 = ta01 * __ldg(fcw + 192 + d1)  + ta02 * __ldg(fcw + 192 + d2)
             + ta11 * __ldg(fcw + 256 + d1)  + ta12 * __ldg(fcw + 256 + d2)
             + f1   * __ldg(fcw + 320 + d1)  + f2   * __ldg(fcw + 320 + d2);
    #pragma unroll
    for (int o = 16; o > 0; o >>= 1) {
        l0 += __shfl_xor_sync(0xffffffffu, l0, o);
        l1 += __shfl_xor_sync(0xffffffffu, l1, o);
    }
    if (lane == 0) {
        l0 += __ldg(fcb + 0);
        l1 += __ldg(fcb + 1);
        float mm  = fmaxf(l0, l1);
        float lse = mm + logf(expf(l0 - mm) + expf(l1 - mm));
        outp[w * 2]     = l0 - lse;
        outp[w * 2 + 1] = l1 - lse;
    }
}

// ---------------- launch ----------------------------------------------------
extern "C" void kernel_launch(void* const* d_in, const int* in_sizes, int n_in,
                              void* d_out, int out_size)
{
    const float* h     = (const float*)d_in[0];
    const int*   src0  = (const int*)  d_in[1];
    const int*   trg0  = (const int*)  d_in[2];
    const int*   src1  = (const int*)  d_in[3];
    const int*   trg1  = (const int*)  d_in[4];
    const float* w0    = (const float*)d_in[5];
    const float* asrc0 = (const float*)d_in[6];
    const float* atrg0 = (const float*)d_in[7];
    const float* w1    = (const float*)d_in[8];
    const float* asrc1 = (const float*)d_in[9];
    const float* atrg1 = (const float*)d_in[10];
    const float* aaw1  = (const float*)d_in[11];
    const float* aaw2  = (const float*)d_in[12];
    const float* aam   = (const float*)d_in[13];
    const float* fcw   = (const float*)d_in[14];
    const float* fcb   = (const float*)d_in[15];
    float* out = (float*)d_out;

    __half *hp0, *hp1;
    float *as_, *at_, *ta, *u, *v;
    int *cnt, *off, *cur, *part, *csr;
    cudaGetSymbolAddress((void**)&hp0,  g_hp0);
    cudaGetSymbolAddress((void**)&hp1,  g_hp1);
    cudaGetSymbolAddress((void**)&as_,  g_as);
    cudaGetSymbolAddress((void**)&at_,  g_at);
    cudaGetSymbolAddress((void**)&ta,   g_ta);
    cudaGetSymbolAddress((void**)&u,    g_u);
    cudaGetSymbolAddress((void**)&v,    g_v);
    cudaGetSymbolAddress((void**)&cnt,  g_cnt);
    cudaGetSymbolAddress((void**)&off,  g_off);
    cudaGetSymbolAddress((void**)&cur,  g_cur);
    cudaGetSymbolAddress((void**)&part, g_part);
    cudaGetSymbolAddress((void**)&csr,  g_csr);

    const int SM128 = (64 * 132 + 64 * 128) * 4;
    const int SM64  = (64 * 132 + 64 * 64)  * 4;
    cudaFuncSetAttribute(gemm_hp_fused, cudaFuncAttributeMaxDynamicSharedMemorySize, SM128);
    cudaFuncSetAttribute(gemm_head,     cudaFuncAttributeMaxDynamicSharedMemorySize, SM64);

    const int EDGE4_BLK = (2 * (N_EDGES / 4) + 255) / 256;   // 3125
    const int GATH_BLK  = (NT2 * 32 + 255) / 256;
    const int HEAD_BLK  = NUSER * 32 / 256;

    // CSR build for both layers (hist/scatter: 4 edges per thread)
    zero_cnt_kernel<<<(NT2 + 255) / 256, 256>>>(cnt);
    hist_kernel<<<EDGE4_BLK, 256>>>(trg0, trg1, cnt);
    scan1_kernel<<<NPART, 256>>>(cnt, off, part);
    scan2_kernel<<<1, 256>>>(part);
    scan3_kernel<<<(NT2 + 255) / 256, 256>>>(off, part, cur);
    scatter_kernel<<<EDGE4_BLK, 256>>>(src0, trg0, src1, trg1, cur, csr);

    // hp GEMMs (both layers) with fused attention logits
    dim3 ggrid((N_NODES + 127) / 128, 2);
    gemm_hp_fused<<<ggrid, 256, SM128>>>(h, w0, w1, asrc0, atrg0, asrc1, atrg1,
                                         hp0, hp1, as_, at_, N_NODES);

    // gather both layers
    gather_kernel<<<GATH_BLK, 256>>>(csr, off, cnt, as_, at_, hp0, hp1, ta);

    // head GEMMs (merged) + head
    dim3 hgrid((NUSER * 2 + 127) / 128, 2);
    gemm_head<<<hgrid, 256, SM64>>>(h, aaw1, u, NUSER, ta, aaw2, v, NUSER * 2);
    head_kernel<<<HEAD_BLK, 256>>>(u, v, ta, aam, fcw, fcb, out);

    (void)in_sizes; (void)n_in; (void)out_size;
}

// round 14
// speedup vs baseline: 1.7171x; 1.7171x over previous
#include <cuda_runtime.h>
#include <cuda_fp16.h>
#include <math.h>

#define N_NODES 100000
#define N_EDGES 1600000
#define NUSER   90000
#define NT2     (2 * NUSER)            // merged bucket count = 180000
#define SCAN_CHUNK 1024
#define NPART   ((NT2 + SCAN_CHUNK - 1) / SCAN_CHUNK)   // 176

// ---------------- scratch (device globals; no allocation allowed) ----------
__device__ __align__(16) __half g_hp0[N_NODES * 128];
__device__ __align__(16) __half g_hp1[N_NODES * 128];
__device__ __align__(16) float g_as [2 * N_NODES * 2];  // [layer][n*2+h]
__device__ __align__(16) float g_at [2 * N_NODES * 2];
__device__ __align__(16) float g_ta [NUSER  * 128];     // type_aware (n, k, d)
__device__ __align__(16) float g_u  [NUSER  * 64];
__device__ __align__(16) float g_v  [NUSER  * 128];
__device__ __align__(16) int   g_cnt[NT2];              // counts
__device__ __align__(16) int   g_off[NT2];              // CSR offsets
__device__ __align__(16) int   g_cur[NT2];              // scatter cursors
__device__ __align__(16) int   g_part[256];
__device__ __align__(16) int   g_csr[2 * N_EDGES];      // bucketed src ids

// ---------------- tf32 helpers ----------------------------------------------
__device__ __forceinline__ unsigned f2tf32(float f)
{
    unsigned u;
    asm("cvt.rna.tf32.f32 %0, %1;" : "=r"(u) : "f"(f));
    return u;
}

__device__ __forceinline__ void mma_tf32(float d[4],
                                         unsigned a0, unsigned a1,
                                         unsigned a2, unsigned a3,
                                         unsigned b0, unsigned b1)
{
    asm volatile(
        "mma.sync.aligned.m16n8k8.row.col.f32.tf32.tf32.f32 "
        "{%0,%1,%2,%3}, {%4,%5,%6,%7}, {%8,%9}, {%0,%1,%2,%3};"
        : "+f"(d[0]), "+f"(d[1]), "+f"(d[2]), "+f"(d[3])
        : "r"(a0), "r"(a1), "r"(a2), "r"(a3), "r"(b0), "r"(b1));
}

// ---------------- fused hp GEMM (tf32 tensor core) + attn logits -------------
// 128x128x64 per block. 8 warps as 2(M) x 4(N); warp tile 64x32.
// smem: As[128][68] fp32, Bs[64][136] fp32, pas[4][128], pat[4][128]
#define LDA_T 68
#define LDB_T 136
#define SM_HP ((128 * LDA_T + 64 * LDB_T + 2 * 4 * 128) * 4)   // 73728 B

__global__ __launch_bounds__(256)
void gemm_hp_fused(const float* __restrict__ A,
                   const float* __restrict__ W0, const float* __restrict__ W1,
                   const float* __restrict__ asrc0, const float* __restrict__ atrg0,
                   const float* __restrict__ asrc1, const float* __restrict__ atrg1,
                   __half* __restrict__ hp0, __half* __restrict__ hp1,
                   float* __restrict__ asOut, float* __restrict__ atOut, int M)
{
    const int layer = blockIdx.y;
    const float* Braw = layer ? W1 : W0;
    const float* aS   = layer ? asrc1 : asrc0;
    const float* aT   = layer ? atrg1 : atrg0;
    __half* hpL = layer ? hp1 : hp0;

    extern __shared__ float smem[];
    float* As  = smem;                          // [128][68]
    float* Bs  = smem + 128 * LDA_T;            // [64][136]
    float* pas = smem + 128 * LDA_T + 64 * LDB_T;   // [4][128]
    float* pat = pas + 4 * 128;                 // [4][128]

    const int t    = threadIdx.x;
    const int row0 = blockIdx.x * 128;

    // load B[k][c] (c = head*64 + f)
    #pragma unroll 4
    for (int i = t; i < 64 * 128; i += 256) {
        int kk = i >> 7, c = i & 127;
        Bs[kk * LDB_T + c] = Braw[(c >> 6) * 4096 + kk * 64 + (c & 63)];
    }
    // load A rows (row-major, no transpose)
    #pragma unroll 4
    for (int i = t; i < 128 * 16; i += 256) {
        int r  = i >> 4;
        int k4 = (i & 15) << 2;
        float4 a = make_float4(0.f, 0.f, 0.f, 0.f);
        if (row0 + r < M) a = *(const float4*)(A + (size_t)(row0 + r) * 64 + k4);
        *(float4*)(As + r * LDA_T + k4) = a;
    }
    __syncthreads();

    const int wid   = t >> 5;
    const int lane  = t & 31;
    const int warpM = wid >> 2;        // 0..1
    const int warpN = wid & 3;         // 0..3
    const int g     = lane >> 2;       // 0..7
    const int tg    = lane & 3;        // 0..3
    const int m0    = warpM * 64;
    const int n0    = warpN * 32;

    float acc[4][4][4];
    #pragma unroll
    for (int m = 0; m < 4; m++)
        #pragma unroll
        for (int n = 0; n < 4; n++)
            #pragma unroll
            for (int j = 0; j < 4; j++) acc[m][n][j] = 0.f;

    #pragma unroll
    for (int ks = 0; ks < 8; ks++) {
        int k0 = ks * 8;
        unsigned areg[4][4];
        #pragma unroll
        for (int m = 0; m < 4; m++) {
            const float* Ap = As + (m0 + m * 16) * LDA_T + k0;
            areg[m][0] = f2tf32(Ap[g * LDA_T + tg]);
            areg[m][1] = f2tf32(Ap[(g + 8) * LDA_T + tg]);
            areg[m][2] = f2tf32(Ap[g * LDA_T + tg + 4]);
            areg[m][3] = f2tf32(Ap[(g + 8) * LDA_T + tg + 4]);
        }
        unsigned breg[4][2];
        #pragma unroll
        for (int n = 0; n < 4; n++) {
            const float* Bp = Bs + k0 * LDB_T + n0 + n * 8;
            breg[n][0] = f2tf32(Bp[tg * LDB_T + g]);
            breg[n][1] = f2tf32(Bp[(tg + 4) * LDB_T + g]);
        }
        #pragma unroll
        for (int m = 0; m < 4; m++)
            #pragma unroll
            for (int n = 0; n < 4; n++)
                mma_tf32(acc[m][n], areg[m][0], areg[m][1], areg[m][2], areg[m][3],
                         breg[n][0], breg[n][1]);
    }

    // ---- store hp in fp16 (c0/c1 = adjacent cols, rows g and g+8) ----
    #pragma unroll
    for (int m = 0; m < 4; m++) {
        int r1 = row0 + m0 + m * 16 + g;
        int r2 = r1 + 8;
        #pragma unroll
        for (int n = 0; n < 4; n++) {
            int col = n0 + n * 8 + 2 * tg;
            if (r1 < M) {
                __half2 h2 = __floats2half2_rn(acc[m][n][0], acc[m][n][1]);
                *(unsigned*)(hpL + (size_t)r1 * 128 + col) = *(unsigned*)&h2;
            }
            if (r2 < M) {
                __half2 h2 = __floats2half2_rn(acc[m][n][2], acc[m][n][3]);
                *(unsigned*)(hpL + (size_t)r2 * 128 + col) = *(unsigned*)&h2;
            }
        }
    }

    // ---- attention logits: per-lane partial dot, reduce over tg, cross-warp
    float2 sv2[4], tv2[4];
    #pragma unroll
    for (int n = 0; n < 4; n++) {
        int col = n0 + n * 8 + 2 * tg;
        sv2[n] = make_float2(aS[col], aS[col + 1]);
        tv2[n] = make_float2(aT[col], aT[col + 1]);
    }
    #pragma unroll
    for (int m = 0; m < 4; m++) {
        float pa0 = 0.f, pa1 = 0.f, pt0 = 0.f, pt1 = 0.f;
        #pragma unroll
        for (int n = 0; n < 4; n++) {
            pa0 = fmaf(acc[m][n][0], sv2[n].x, fmaf(acc[m][n][1], sv2[n].y, pa0));
            pa1 = fmaf(acc[m][n][2], sv2[n].x, fmaf(acc[m][n][3], sv2[n].y, pa1));
            pt0 = fmaf(acc[m][n][0], tv2[n].x, fmaf(acc[m][n][1], tv2[n].y, pt0));
            pt1 = fmaf(acc[m][n][2], tv2[n].x, fmaf(acc[m][n][3], tv2[n].y, pt1));
        }
        #pragma unroll
        for (int o = 1; o < 4; o <<= 1) {
            pa0 += __shfl_xor_sync(0xffffffffu, pa0, o);
            pa1 += __shfl_xor_sync(0xffffffffu, pa1, o);
            pt0 += __shfl_xor_sync(0xffffffffu, pt0, o);
            pt1 += __shfl_xor_sync(0xffffffffu, pt1, o);
        }
        if (tg == 0) {
            int r = m0 + m * 16 + g;
            pas[warpN * 128 + r]     = pa0;
            pas[warpN * 128 + r + 8] = pa1;
            pat[warpN * 128 + r]     = pt0;
            pat[warpN * 128 + r + 8] = pt1;
        }
    }
    __syncthreads();

    if (t < 128) {
        int row = row0 + t;
        if (row < M) {
            int abase = layer * N_NODES * 2;
            asOut[abase + row * 2 + 0] = pas[t]       + pas[128 + t];
            asOut[abase + row * 2 + 1] = pas[256 + t] + pas[384 + t];
            atOut[abase + row * 2 + 0] = pat[t]       + pat[128 + t];
            atOut[abase + row * 2 + 1] = pat[256 + t] + pat[384 + t];
        }
    }
}

// ---------------- head GEMMs merged: y=0 -> u = h@aaw1^T ; y=1 -> v = ta@aaw2^T
__global__ __launch_bounds__(256)
void gemm_head(const float* __restrict__ A0, const float* __restrict__ B0,
               float* __restrict__ C0, int M0,
               const float* __restrict__ A1, const float* __restrict__ B1,
               float* __restrict__ C1, int M1)
{
    constexpr int P   = 64;
    constexpr int BM  = 128;
    constexpr int LDA = BM + 4;

    const int sel = blockIdx.y;
    const float* A    = sel ? A1 : A0;
    const float* Braw = sel ? B1 : B0;
    float*       C    = sel ? C1 : C0;
    const int    M    = sel ? M1 : M0;

    const int row0 = blockIdx.x * BM;
    if (row0 >= M) return;

    extern __shared__ float smem[];
    float* As = smem;
    float* Bs = smem + 64 * LDA;

    const int t = threadIdx.x;

    #pragma unroll 4
    for (int i = t; i < 64 * P; i += 256) {
        int kk = i / P, c = i % P;
        Bs[kk * P + c] = Braw[c * 64 + kk];
    }
    #pragma unroll 4
    for (int i = t; i < BM * 16; i += 256) {
        int r  = i >> 4;
        int k4 = (i & 15) << 2;
        float4 a = make_float4(0.f, 0.f, 0.f, 0.f);
        if (row0 + r < M) a = *(const float4*)(A + (size_t)(row0 + r) * 64 + k4);
        As[(k4 + 0) * LDA + r] = a.x;
        As[(k4 + 1) * LDA + r] = a.y;
        As[(k4 + 2) * LDA + r] = a.z;
        As[(k4 + 3) * LDA + r] = a.w;
    }
    __syncthreads();

    const int cg = t & 15;
    const int rg = t >> 4;

    float acc[8][4];
    #pragma unroll
    for (int r = 0; r < 8; r++)
        #pragma unroll
        for (int c = 0; c < 4; c++) acc[r][c] = 0.f;

    #pragma unroll
    for (int k = 0; k < 64; k++) {
        float4 a0 = *(const float4*)(As + k * LDA + rg * 8);
        float4 a1 = *(const float4*)(As + k * LDA + rg * 8 + 4);
        float a[8] = {a0.x, a0.y, a0.z, a0.w, a1.x, a1.y, a1.z, a1.w};
        float4 b0 = *(const float4*)(Bs + k * P + cg * 4);
        float b[4] = {b0.x, b0.y, b0.z, b0.w};
        #pragma unroll
        for (int r = 0; r < 8; r++)
            #pragma unroll
            for (int c = 0; c < 4; c++)
                acc[r][c] = fmaf(a[r], b[c], acc[r][c]);
    }

    #pragma unroll
    for (int r = 0; r < 8; r++) {
        int row = row0 + rg * 8 + r;
        if (row < M) {
            float4 o = make_float4(acc[r][0], acc[r][1], acc[r][2], acc[r][3]);
            *(float4*)(C + (size_t)row * P + cg * 4) = o;
        }
    }
}

// ---------------- CSR build --------------------------------------------------
__global__ void zero_cnt_kernel(int* __restrict__ cnt)
{
    int i = blockIdx.x * blockDim.x + threadIdx.x;
    if (i < NT2) cnt[i] = 0;
}

__global__ __launch_bounds__(256)
void hist_kernel(const int* __restrict__ trgA, const int* __restrict__ trgB,
                 int* __restrict__ cnt)
{
    int i = blockIdx.x * blockDim.x + threadIdx.x;
    if (i >= 2 * N_EDGES) return;
    int layer = (i >= N_EDGES);
    const int* trg = layer ? trgB : trgA;
    int t = __ldg(trg + (i - layer * N_EDGES));
    if (t < NUSER) atomicAdd(cnt + layer * NUSER + t, 1);
}

__global__ __launch_bounds__(256)
void scan1_kernel(const int* __restrict__ cnt, int* __restrict__ off,
                  int* __restrict__ part)
{
    __shared__ int s[256];
    int t = threadIdx.x, b = blockIdx.x;
    int i0 = b * SCAN_CHUNK + t * 4;
    int c[4];
    #pragma unroll
    for (int j = 0; j < 4; j++) c[j] = (i0 + j < NT2) ? cnt[i0 + j] : 0;
    int tot = c[0] + c[1] + c[2] + c[3];
    s[t] = tot;
    __syncthreads();
    int v = s[t];
    #pragma unroll
    for (int o = 1; o < 256; o <<= 1) {
        int u = (t >= o) ? s[t - o] : 0;
        __syncthreads();
        v += u; s[t] = v;
        __syncthreads();
    }
    int excl = v - tot;
    #pragma unroll
    for (int j = 0; j < 4; j++) {
        if (i0 + j < NT2) off[i0 + j] = excl;
        excl += c[j];
    }
    if (t == 255) part[b] = v;
}

__global__ void scan2_kernel(int* __restrict__ part)
{
    __shared__ int s[256];
    int t = threadIdx.x;
    int own = (t < NPART) ? part[t] : 0;
    s[t] = own;
    __syncthreads();
    int v = s[t];
    #pragma unroll
    for (int o = 1; o < 256; o <<= 1) {
        int u = (t >= o) ? s[t - o] : 0;
        __syncthreads();
        v += u; s[t] = v;
        __syncthreads();
    }
    if (t < NPART) part[t] = v - own;
}

// add chunk base AND initialize scatter cursor
__global__ void scan3_kernel(int* __restrict__ off, const int* __restrict__ part,
                             int* __restrict__ cur)
{
    int i = blockIdx.x * blockDim.x + threadIdx.x;
    if (i < NT2) {
        int o = off[i] + part[i / SCAN_CHUNK];
        off[i] = o;
        cur[i] = o;
    }
}

__global__ __launch_bounds__(256)
void scatter_kernel(const int* __restrict__ srcA, const int* __restrict__ trgA,
                    const int* __restrict__ srcB, const int* __restrict__ trgB,
                    int* __restrict__ cur, int* __restrict__ csr)
{
    int i = blockIdx.x * blockDim.x + threadIdx.x;
    if (i >= 2 * N_EDGES) return;
    int layer = (i >= N_EDGES);
    int e = i - layer * N_EDGES;
    const int* trg = layer ? trgB : trgA;
    const int* src = layer ? srcB : srcA;
    int t = __ldg(trg + e);
    if (t >= NUSER) return;
    int pos = atomicAdd(cur + layer * NUSER + t, 1);
    csr[pos] = __ldg(src + e);
}

// ---------------- gather: warp per (layer, target), unrolled x2 (R11) -------
__global__ __launch_bounds__(256)
void gather_kernel(const int* __restrict__ csr, const int* __restrict__ off,
                   const int* __restrict__ cnt,
                   const float* __restrict__ as_, const float* __restrict__ at_,
                   const __half* __restrict__ hp0, const __half* __restrict__ hp1,
                   float* __restrict__ ta)
{
    int w    = (blockIdx.x * blockDim.x + threadIdx.x) >> 5;
    int lane = threadIdx.x & 31;
    if (w >= NT2) return;
    int layer = (w >= NUSER);
    int t = w - layer * NUSER;
    const __half* hpL = layer ? hp1 : hp0;
    int abase = layer * N_NODES * 2;

    int grp  = lane >> 4;        // which edge of the pair
    int sub  = lane & 15;        // 16-lane slot within edge
    int hsel = sub >> 3;         // head of this lane

    float at_own = __ldg(at_ + abase + 2 * t + hsel);
    int start = __ldg(off + w);
    int n     = __ldg(cnt + w);

    float acc[8];
    #pragma unroll
    for (int j = 0; j < 8; j++) acc[j] = 0.f;
    float den = 0.f;

    int i = 0;
    for (; i + 4 <= n; i += 4) {
        int sA = __ldg(csr + start + i + grp);
        int sB = __ldg(csr + start + i + 2 + grp);
        float eA = __ldg(as_ + abase + 2 * sA + hsel) + at_own;
        float eB = __ldg(as_ + abase + 2 * sB + hsel) + at_own;
        eA = (eA > 0.f) ? eA : 0.2f * eA;
        eB = (eB > 0.f) ? eB : 0.2f * eB;
        float wA = __expf(eA);
        float wB = __expf(eB);
        uint4 rA = *(const uint4*)(hpL + (size_t)sA * 128 + sub * 8);
        uint4 rB = *(const uint4*)(hpL + (size_t)sB * 128 + sub * 8);
        den += wA + wB;
        float2 f;
        f = __half22float2(*reinterpret_cast<__half2*>(&rA.x));
        acc[0] = fmaf(wA, f.x, acc[0]); acc[1] = fmaf(wA, f.y, acc[1]);
        f = __half22float2(*reinterpret_cast<__half2*>(&rA.y));
        acc[2] = fmaf(wA, f.x, acc[2]); acc[3] = fmaf(wA, f.y, acc[3]);
        f = __half22float2(*reinterpret_cast<__half2*>(&rA.z));
        acc[4] = fmaf(wA, f.x, acc[4]); acc[5] = fmaf(wA, f.y, acc[5]);
        f = __half22float2(*reinterpret_cast<__half2*>(&rA.w));
        acc[6] = fmaf(wA, f.x, acc[6]); acc[7] = fmaf(wA, f.y, acc[7]);
        f = __half22float2(*reinterpret_cast<__half2*>(&rB.x));
        acc[0] = fmaf(wB, f.x, acc[0]); acc[1] = fmaf(wB, f.y, acc[1]);
        f = __half22float2(*reinterpret_cast<__half2*>(&rB.y));
        acc[2] = fmaf(wB, f.x, acc[2]); acc[3] = fmaf(wB, f.y, acc[3]);
        f = __half22float2(*reinterpret_cast<__half2*>(&rB.z));
        acc[4] = fmaf(wB, f.x, acc[4]); acc[5] = fmaf(wB, f.y, acc[5]);
        f = __half22float2(*reinterpret_cast<__half2*>(&rB.w));
        acc[6] = fmaf(wB, f.x, acc[6]); acc[7] = fmaf(wB, f.y, acc[7]);
    }
    for (; i < n; i += 2) {
        int idx = i + grp;
        bool valid = idx < n;
        int sidx = valid ? idx : i;
        int s = __ldg(csr + start + sidx);
        float e = __ldg(as_ + abase + 2 * s + hsel) + at_own;
        e = (e > 0.f) ? e : 0.2f * e;
        float wgt = valid ? __expf(e) : 0.f;
        den += wgt;
        uint4 r = *(const uint4*)(hpL + (size_t)s * 128 + sub * 8);
        float2 f;
        f = __half22float2(*reinterpret_cast<__half2*>(&r.x));
        acc[0] = fmaf(wgt, f.x, acc[0]); acc[1] = fmaf(wgt, f.y, acc[1]);
        f = __half22float2(*reinterpret_cast<__half2*>(&r.y));
        acc[2] = fmaf(wgt, f.x, acc[2]); acc[3] = fmaf(wgt, f.y, acc[3]);
        f = __half22float2(*reinterpret_cast<__half2*>(&r.z));
        acc[4] = fmaf(wgt, f.x, acc[4]); acc[5] = fmaf(wgt, f.y, acc[5]);
        f = __half22float2(*reinterpret_cast<__half2*>(&r.w));
        acc[6] = fmaf(wgt, f.x, acc[6]); acc[7] = fmaf(wgt, f.y, acc[7]);
    }

    den += __shfl_xor_sync(0xffffffffu, den, 16);
    #pragma unroll
    for (int j = 0; j < 8; j++)
        acc[j] += __shfl_xor_sync(0xffffffffu, acc[j], 16);

    float inv = 1.f / (den + 1e-16f);
    #pragma unroll
    for (int j = 0; j < 8; j++) acc[j] *= inv;

    float other[8];
    #pragma unroll
    for (int j = 0; j < 8; j++)
        other[j] = __shfl_xor_sync(0xffffffffu, acc[j], 8);

    if (grp == 0 && hsel == 0) {
        float4 r0 = make_float4(0.5f * (acc[0] + other[0]), 0.5f * (acc[1] + other[1]),
                                0.5f * (acc[2] + other[2]), 0.5f * (acc[3] + other[3]));
        float4 r1 = make_float4(0.5f * (acc[4] + other[4]), 0.5f * (acc[5] + other[5]),
                                0.5f * (acc[6] + other[6]), 0.5f * (acc[7] + other[7]));
        float* dst = ta + (size_t)t * 128 + layer * 64 + sub * 8;
        *(float4*)(dst)     = r0;
        *(float4*)(dst + 4) = r1;
    }
}

// ---------------- head: tanh-attention fusion + FC + log_softmax ------------
__global__ __launch_bounds__(256)
void head_kernel(const float* __restrict__ u, const float* __restrict__ v,
                 const float* __restrict__ ta,
                 const float* __restrict__ aam, const float* __restrict__ fcw,
                 const float* __restrict__ fcb, float* __restrict__ outp)
{
    int w    = (blockIdx.x * blockDim.x + threadIdx.x) >> 5;
    int lane = threadIdx.x & 31;
    if (w >= NUSER) return;
    int d1 = lane, d2 = lane + 32;

    float u1   = u[w * 64 + d1],            u2   = u[w * 64 + d2];
    float v01  = v[(2*w) * 64 + d1],        v02  = v[(2*w) * 64 + d2];
    float v11  = v[(2*w+1) * 64 + d1],      v12  = v[(2*w+1) * 64 + d2];
    float ta01 = ta[w * 128 + d1],          ta02 = ta[w * 128 + d2];
    float ta11 = ta[w * 128 + 64 + d1],     ta12 = ta[w * 128 + 64 + d2];
    float am1  = __ldg(aam + d1),           am2  = __ldg(aam + d2);

    float s0 = tanhf(u1 + v01) * am1 + tanhf(u2 + v02) * am2;
    float s1 = tanhf(u1 + v11) * am1 + tanhf(u2 + v12) * am2;
    #pragma unroll
    for (int o = 16; o > 0; o >>= 1) {
        s0 += __shfl_xor_sync(0xffffffffu, s0, o);
        s1 += __shfl_xor_sync(0xffffffffu, s1, o);
    }
    float m  = fmaxf(s0, s1);
    float e0 = expf(s0 - m), e1 = expf(s1 - m);
    float rb = 1.f / (e0 + e1);
    float b0 = e0 * rb, b1 = e1 * rb;

    float f1 = b0 * ta01 + b1 * ta11;
    float f2 = b0 * ta02 + b1 * ta12;

    float l0 = ta01 * __ldg(fcw + d1)        + ta02 * __ldg(fcw + d2)
             + ta11 * __ldg(fcw + 64 + d1)   + ta12 * __ldg(fcw + 64 + d2)
             + f1   * __ldg(fcw + 128 + d1)  + f2   * __ldg(fcw + 128 + d2);
    float l1 = ta01 * __ldg(fcw + 192 + d1)  + ta02 * __ldg(fcw + 192 + d2)
             + ta11 * __ldg(fcw + 256 + d1)  + ta12 * __ldg(fcw + 256 + d2)
             + f1   * __ldg(fcw + 320 + d1)  + f2   * __ldg(fcw + 320 + d2);
    #pragma unroll
    for (int o = 16; o > 0; o >>= 1) {
        l0 += __shfl_xor_sync(0xffffffffu, l0, o);
        l1 += __shfl_xor_sync(0xffffffffu, l1, o);
    }
    if (lane == 0) {
        l0 += __ldg(fcb + 0);
        l1 += __ldg(fcb + 1);
        float mm  = fmaxf(l0, l1);
        float lse = mm + logf(expf(l0 - mm) + expf(l1 - mm));
        outp[w * 2]     = l0 - lse;
        outp[w * 2 + 1] = l1 - lse;
    }
}

// ---------------- launch ----------------------------------------------------
extern "C" void kernel_launch(void* const* d_in, const int* in_sizes, int n_in,
                              void* d_out, int out_size)
{
    const float* h     = (const float*)d_in[0];
    const int*   src0  = (const int*)  d_in[1];
    const int*   trg0  = (const int*)  d_in[2];
    const int*   src1  = (const int*)  d_in[3];
    const int*   trg1  = (const int*)  d_in[4];
    const float* w0    = (const float*)d_in[5];
    const float* asrc0 = (const float*)d_in[6];
    const float* atrg0 = (const float*)d_in[7];
    const float* w1    = (const float*)d_in[8];
    const float* asrc1 = (const float*)d_in[9];
    const float* atrg1 = (const float*)d_in[10];
    const float* aaw1  = (const float*)d_in[11];
    const float* aaw2  = (const float*)d_in[12];
    const float* aam   = (const float*)d_in[13];
    const float* fcw   = (const float*)d_in[14];
    const float* fcb   = (const float*)d_in[15];
    float* out = (float*)d_out;

    __half *hp0, *hp1;
    float *as_, *at_, *ta, *u, *v;
    int *cnt, *off, *cur, *part, *csr;
    cudaGetSymbolAddress((void**)&hp0,  g_hp0);
    cudaGetSymbolAddress((void**)&hp1,  g_hp1);
    cudaGetSymbolAddress((void**)&as_,  g_as);
    cudaGetSymbolAddress((void**)&at_,  g_at);
    cudaGetSymbolAddress((void**)&ta,   g_ta);
    cudaGetSymbolAddress((void**)&u,    g_u);
    cudaGetSymbolAddress((void**)&v,    g_v);
    cudaGetSymbolAddress((void**)&cnt,  g_cnt);
    cudaGetSymbolAddress((void**)&off,  g_off);
    cudaGetSymbolAddress((void**)&cur,  g_cur);
    cudaGetSymbolAddress((void**)&part, g_part);
    cudaGetSymbolAddress((void**)&csr,  g_csr);

    const int SM64 = (64 * 132 + 64 * 64) * 4;
    cudaFuncSetAttribute(gemm_hp_fused, cudaFuncAttributeMaxDynamicSharedMemorySize, SM_HP);
    cudaFuncSetAttribute(gemm_head,     cudaFuncAttributeMaxDynamicSharedMemorySize, SM64);

    const int EDGE2_BLK = (2 * N_EDGES + 255) / 256;
    const int GATH_BLK  = (NT2 * 32 + 255) / 256;
    const int HEAD_BLK  = NUSER * 32 / 256;

    // CSR build for both layers
    zero_cnt_kernel<<<(NT2 + 255) / 256, 256>>>(cnt);
    hist_kernel<<<EDGE2_BLK, 256>>>(trg0, trg1, cnt);
    scan1_kernel<<<NPART, 256>>>(cnt, off, part);
    scan2_kernel<<<1, 256>>>(part);
    scan3_kernel<<<(NT2 + 255) / 256, 256>>>(off, part, cur);
    scatter_kernel<<<EDGE2_BLK, 256>>>(src0, trg0, src1, trg1, cur, csr);

    // hp GEMMs (both layers, tf32 tensor core) with fused attention logits
    dim3 ggrid((N_NODES + 127) / 128, 2);
    gemm_hp_fused<<<ggrid, 256, SM_HP>>>(h, w0, w1, asrc0, atrg0, asrc1, atrg1,
                                         hp0, hp1, as_, at_, N_NODES);

    // gather both layers
    gather_kernel<<<GATH_BLK, 256>>>(csr, off, cnt, as_, at_, hp0, hp1, ta);

    // head GEMMs (merged) + head
    dim3 hgrid((NUSER * 2 + 127) / 128, 2);
    gemm_head<<<hgrid, 256, SM64>>>(h, aaw1, u, NUSER, ta, aaw2, v, NUSER * 2);
    head_kernel<<<HEAD_BLK, 256>>>(u, v, ta, aam, fcw, fcb, out);

    (void)in_sizes; (void)n_in; (void)out_size;
}

// round 15
// speedup vs baseline: 1.8558x; 1.0808x over previous
#include <cuda_runtime.h>
#include <cuda_fp16.h>
#include <math.h>

#define N_NODES 100000
#define N_EDGES 1600000
#define NUSER   90000
#define NT2     (2 * NUSER)            // merged bucket count = 180000
#define SCAN_CHUNK 1024
#define NPART   ((NT2 + SCAN_CHUNK - 1) / SCAN_CHUNK)   // 176

// ---------------- scratch (device globals; no allocation allowed) ----------
__device__ __align__(16) __half g_hp0[N_NODES * 128];
__device__ __align__(16) __half g_hp1[N_NODES * 128];
__device__ __align__(16) float g_as [2 * N_NODES * 2];  // [layer][n*2+h]
__device__ __align__(16) float g_at [2 * N_NODES * 2];
__device__ __align__(16) float g_ta [NUSER  * 128];     // type_aware (n, k, d)
__device__ __align__(16) float g_u  [NUSER  * 64];
__device__ __align__(16) float g_v  [NUSER  * 128];
__device__ __align__(16) int   g_cnt[NT2];              // counts
__device__ __align__(16) int   g_off[NT2];              // CSR offsets
__device__ __align__(16) int   g_cur[NT2];              // scatter cursors
__device__ __align__(16) int   g_part[256];
__device__ __align__(16) int   g_csr[2 * N_EDGES];      // bucketed src ids

// ---------------- tf32 helpers ----------------------------------------------
__device__ __forceinline__ unsigned f2tf32(float f)
{
    unsigned u;
    asm("cvt.rna.tf32.f32 %0, %1;" : "=r"(u) : "f"(f));
    return u;
}

__device__ __forceinline__ void mma_tf32(float d[4],
                                         unsigned a0, unsigned a1,
                                         unsigned a2, unsigned a3,
                                         unsigned b0, unsigned b1)
{
    asm volatile(
        "mma.sync.aligned.m16n8k8.row.col.f32.tf32.tf32.f32 "
        "{%0,%1,%2,%3}, {%4,%5,%6,%7}, {%8,%9}, {%0,%1,%2,%3};"
        : "+f"(d[0]), "+f"(d[1]), "+f"(d[2]), "+f"(d[3])
        : "r"(a0), "r"(a1), "r"(a2), "r"(a3), "r"(b0), "r"(b1));
}

// ---------------- fused hp GEMM (tf32 tensor core) + attn logits -------------
// 128x128x64 per block. 8 warps as 2(M) x 4(N); warp tile 64x32.
#define LDA_T 68
#define LDB_T 136
#define SM_HP ((128 * LDA_T + 64 * LDB_T + 2 * 4 * 128) * 4)   // 73728 B

__global__ __launch_bounds__(256)
void gemm_hp_fused(const float* __restrict__ A,
                   const float* __restrict__ W0, const float* __restrict__ W1,
                   const float* __restrict__ asrc0, const float* __restrict__ atrg0,
                   const float* __restrict__ asrc1, const float* __restrict__ atrg1,
                   __half* __restrict__ hp0, __half* __restrict__ hp1,
                   float* __restrict__ asOut, float* __restrict__ atOut, int M)
{
    const int layer = blockIdx.y;
    const float* Braw = layer ? W1 : W0;
    const float* aS   = layer ? asrc1 : asrc0;
    const float* aT   = layer ? atrg1 : atrg0;
    __half* hpL = layer ? hp1 : hp0;

    extern __shared__ float smem[];
    float* As  = smem;                          // [128][68]
    float* Bs  = smem + 128 * LDA_T;            // [64][136]
    float* pas = smem + 128 * LDA_T + 64 * LDB_T;   // [4][128]
    float* pat = pas + 4 * 128;                 // [4][128]

    const int t    = threadIdx.x;
    const int row0 = blockIdx.x * 128;

    #pragma unroll 4
    for (int i = t; i < 64 * 128; i += 256) {
        int kk = i >> 7, c = i & 127;
        Bs[kk * LDB_T + c] = Braw[(c >> 6) * 4096 + kk * 64 + (c & 63)];
    }
    #pragma unroll 4
    for (int i = t; i < 128 * 16; i += 256) {
        int r  = i >> 4;
        int k4 = (i & 15) << 2;
        float4 a = make_float4(0.f, 0.f, 0.f, 0.f);
        if (row0 + r < M) a = *(const float4*)(A + (size_t)(row0 + r) * 64 + k4);
        *(float4*)(As + r * LDA_T + k4) = a;
    }
    __syncthreads();

    const int wid   = t >> 5;
    const int lane  = t & 31;
    const int warpM = wid >> 2;
    const int warpN = wid & 3;
    const int g     = lane >> 2;
    const int tg    = lane & 3;
    const int m0    = warpM * 64;
    const int n0    = warpN * 32;

    float acc[4][4][4];
    #pragma unroll
    for (int m = 0; m < 4; m++)
        #pragma unroll
        for (int n = 0; n < 4; n++)
            #pragma unroll
            for (int j = 0; j < 4; j++) acc[m][n][j] = 0.f;

    #pragma unroll
    for (int ks = 0; ks < 8; ks++) {
        int k0 = ks * 8;
        unsigned areg[4][4];
        #pragma unroll
        for (int m = 0; m < 4; m++) {
            const float* Ap = As + (m0 + m * 16) * LDA_T + k0;
            areg[m][0] = f2tf32(Ap[g * LDA_T + tg]);
            areg[m][1] = f2tf32(Ap[(g + 8) * LDA_T + tg]);
            areg[m][2] = f2tf32(Ap[g * LDA_T + tg + 4]);
            areg[m][3] = f2tf32(Ap[(g + 8) * LDA_T + tg + 4]);
        }
        unsigned breg[4][2];
        #pragma unroll
        for (int n = 0; n < 4; n++) {
            const float* Bp = Bs + k0 * LDB_T + n0 + n * 8;
            breg[n][0] = f2tf32(Bp[tg * LDB_T + g]);
            breg[n][1] = f2tf32(Bp[(tg + 4) * LDB_T + g]);
        }
        #pragma unroll
        for (int m = 0; m < 4; m++)
            #pragma unroll
            for (int n = 0; n < 4; n++)
                mma_tf32(acc[m][n], areg[m][0], areg[m][1], areg[m][2], areg[m][3],
                         breg[n][0], breg[n][1]);
    }

    #pragma unroll
    for (int m = 0; m < 4; m++) {
        int r1 = row0 + m0 + m * 16 + g;
        int r2 = r1 + 8;
        #pragma unroll
        for (int n = 0; n < 4; n++) {
            int col = n0 + n * 8 + 2 * tg;
            if (r1 < M) {
                __half2 h2 = __floats2half2_rn(acc[m][n][0], acc[m][n][1]);
                *(unsigned*)(hpL + (size_t)r1 * 128 + col) = *(unsigned*)&h2;
            }
            if (r2 < M) {
                __half2 h2 = __floats2half2_rn(acc[m][n][2], acc[m][n][3]);
                *(unsigned*)(hpL + (size_t)r2 * 128 + col) = *(unsigned*)&h2;
            }
        }
    }

    float2 sv2[4], tv2[4];
    #pragma unroll
    for (int n = 0; n < 4; n++) {
        int col = n0 + n * 8 + 2 * tg;
        sv2[n] = make_float2(aS[col], aS[col + 1]);
        tv2[n] = make_float2(aT[col], aT[col + 1]);
    }
    #pragma unroll
    for (int m = 0; m < 4; m++) {
        float pa0 = 0.f, pa1 = 0.f, pt0 = 0.f, pt1 = 0.f;
        #pragma unroll
        for (int n = 0; n < 4; n++) {
            pa0 = fmaf(acc[m][n][0], sv2[n].x, fmaf(acc[m][n][1], sv2[n].y, pa0));
            pa1 = fmaf(acc[m][n][2], sv2[n].x, fmaf(acc[m][n][3], sv2[n].y, pa1));
            pt0 = fmaf(acc[m][n][0], tv2[n].x, fmaf(acc[m][n][1], tv2[n].y, pt0));
            pt1 = fmaf(acc[m][n][2], tv2[n].x, fmaf(acc[m][n][3], tv2[n].y, pt1));
        }
        #pragma unroll
        for (int o = 1; o < 4; o <<= 1) {
            pa0 += __shfl_xor_sync(0xffffffffu, pa0, o);
            pa1 += __shfl_xor_sync(0xffffffffu, pa1, o);
            pt0 += __shfl_xor_sync(0xffffffffu, pt0, o);
            pt1 += __shfl_xor_sync(0xffffffffu, pt1, o);
        }
        if (tg == 0) {
            int r = m0 + m * 16 + g;
            pas[warpN * 128 + r]     = pa0;
            pas[warpN * 128 + r + 8] = pa1;
            pat[warpN * 128 + r]     = pt0;
            pat[warpN * 128 + r + 8] = pt1;
        }
    }
    __syncthreads();

    if (t < 128) {
        int row = row0 + t;
        if (row < M) {
            int abase = layer * N_NODES * 2;
            asOut[abase + row * 2 + 0] = pas[t]       + pas[128 + t];
            asOut[abase + row * 2 + 1] = pas[256 + t] + pas[384 + t];
            atOut[abase + row * 2 + 0] = pat[t]       + pat[128 + t];
            atOut[abase + row * 2 + 1] = pat[256 + t] + pat[384 + t];
        }
    }
}

// ---------------- head GEMMs (tf32): C[Mx64] = A[Mx64] @ Braw^T --------------
// 128x64x64 per block. 8 warps as 2(M) x 4(N); warp tile 64x16.
#define LDB_H 72
#define SM_HD ((128 * LDA_T + 64 * LDB_H) * 4)   // 53248 B

__global__ __launch_bounds__(256)
void gemm_head(const float* __restrict__ A0, const float* __restrict__ B0,
               float* __restrict__ C0, int M0,
               const float* __restrict__ A1, const float* __restrict__ B1,
               float* __restrict__ C1, int M1)
{
    const int sel = blockIdx.y;
    const float* A    = sel ? A1 : A0;
    const float* Braw = sel ? B1 : B0;
    float*       C    = sel ? C1 : C0;
    const int    M    = sel ? M1 : M0;

    const int row0 = blockIdx.x * 128;
    if (row0 >= M) return;

    extern __shared__ float smem[];
    float* As = smem;                 // [128][68]
    float* Bs = smem + 128 * LDA_T;   // [64][72]

    const int t = threadIdx.x;

    #pragma unroll 4
    for (int i = t; i < 64 * 64; i += 256) {
        int kk = i >> 6, c = i & 63;
        Bs[kk * LDB_H + c] = Braw[c * 64 + kk];
    }
    #pragma unroll 4
    for (int i = t; i < 128 * 16; i += 256) {
        int r  = i >> 4;
        int k4 = (i & 15) << 2;
        float4 a = make_float4(0.f, 0.f, 0.f, 0.f);
        if (row0 + r < M) a = *(const float4*)(A + (size_t)(row0 + r) * 64 + k4);
        *(float4*)(As + r * LDA_T + k4) = a;
    }
    __syncthreads();

    const int wid   = t >> 5;
    const int lane  = t & 31;
    const int warpM = wid >> 2;        // 0..1
    const int warpN = wid & 3;         // 0..3
    const int g     = lane >> 2;       // 0..7
    const int tg    = lane & 3;        // 0..3
    const int m0    = warpM * 64;
    const int n0    = warpN * 16;

    float acc[4][2][4];
    #pragma unroll
    for (int m = 0; m < 4; m++)
        #pragma unroll
        for (int n = 0; n < 2; n++)
            #pragma unroll
            for (int j = 0; j < 4; j++) acc[m][n][j] = 0.f;

    #pragma unroll
    for (int ks = 0; ks < 8; ks++) {
        int k0 = ks * 8;
        unsigned areg[4][4];
        #pragma unroll
        for (int m = 0; m < 4; m++) {
            const float* Ap = As + (m0 + m * 16) * LDA_T + k0;
            areg[m][0] = f2tf32(Ap[g * LDA_T + tg]);
            areg[m][1] = f2tf32(Ap[(g + 8) * LDA_T + tg]);
            areg[m][2] = f2tf32(Ap[g * LDA_T + tg + 4]);
            areg[m][3] = f2tf32(Ap[(g + 8) * LDA_T + tg + 4]);
        }
        unsigned breg[2][2];
        #pragma unroll
        for (int n = 0; n < 2; n++) {
            const float* Bp = Bs + k0 * LDB_H + n0 + n * 8;
            breg[n][0] = f2tf32(Bp[tg * LDB_H + g]);
            breg[n][1] = f2tf32(Bp[(tg + 4) * LDB_H + g]);
        }
        #pragma unroll
        for (int m = 0; m < 4; m++)
            #pragma unroll
            for (int n = 0; n < 2; n++)
                mma_tf32(acc[m][n], areg[m][0], areg[m][1], areg[m][2], areg[m][3],
                         breg[n][0], breg[n][1]);
    }

    #pragma unroll
    for (int m = 0; m < 4; m++) {
        int r1 = row0 + m0 + m * 16 + g;
        int r2 = r1 + 8;
        #pragma unroll
        for (int n = 0; n < 2; n++) {
            int col = n0 + n * 8 + 2 * tg;
            if (r1 < M) {
                float2 o = make_float2(acc[m][n][0], acc[m][n][1]);
                *(float2*)(C + (size_t)r1 * 64 + col) = o;
            }
            if (r2 < M) {
                float2 o = make_float2(acc[m][n][2], acc[m][n][3]);
                *(float2*)(C + (size_t)r2 * 64 + col) = o;
            }
        }
    }
}

// ---------------- CSR build --------------------------------------------------
__global__ void zero_cnt_kernel(int* __restrict__ cnt)
{
    int i = blockIdx.x * blockDim.x + threadIdx.x;
    if (i < NT2) cnt[i] = 0;
}

__global__ __launch_bounds__(256)
void hist_kernel(const int* __restrict__ trgA, const int* __restrict__ trgB,
                 int* __restrict__ cnt)
{
    int i = blockIdx.x * blockDim.x + threadIdx.x;
    if (i >= 2 * N_EDGES) return;
    int layer = (i >= N_EDGES);
    const int* trg = layer ? trgB : trgA;
    int t = __ldg(trg + (i - layer * N_EDGES));
    if (t < NUSER) atomicAdd(cnt + layer * NUSER + t, 1);
}

__global__ __launch_bounds__(256)
void scan1_kernel(const int* __restrict__ cnt, int* __restrict__ off,
                  int* __restrict__ part)
{
    __shared__ int s[256];
    int t = threadIdx.x, b = blockIdx.x;
    int i0 = b * SCAN_CHUNK + t * 4;
    int c[4];
    #pragma unroll
    for (int j = 0; j < 4; j++) c[j] = (i0 + j < NT2) ? cnt[i0 + j] : 0;
    int tot = c[0] + c[1] + c[2] + c[3];
    s[t] = tot;
    __syncthreads();
    int v = s[t];
    #pragma unroll
    for (int o = 1; o < 256; o <<= 1) {
        int u = (t >= o) ? s[t - o] : 0;
        __syncthreads();
        v += u; s[t] = v;
        __syncthreads();
    }
    int excl = v - tot;
    #pragma unroll
    for (int j = 0; j < 4; j++) {
        if (i0 + j < NT2) off[i0 + j] = excl;
        excl += c[j];
    }
    if (t == 255) part[b] = v;
}

__global__ void scan2_kernel(int* __restrict__ part)
{
    __shared__ int s[256];
    int t = threadIdx.x;
    int own = (t < NPART) ? part[t] : 0;
    s[t] = own;
    __syncthreads();
    int v = s[t];
    #pragma unroll
    for (int o = 1; o < 256; o <<= 1) {
        int u = (t >= o) ? s[t - o] : 0;
        __syncthreads();
        v += u; s[t] = v;
        __syncthreads();
    }
    if (t < NPART) part[t] = v - own;
}

// add chunk base AND initialize scatter cursor
__global__ void scan3_kernel(int* __restrict__ off, const int* __restrict__ part,
                             int* __restrict__ cur)
{
    int i = blockIdx.x * blockDim.x + threadIdx.x;
    if (i < NT2) {
        int o = off[i] + part[i / SCAN_CHUNK];
        off[i] = o;
        cur[i] = o;
    }
}

__global__ __launch_bounds__(256)
void scatter_kernel(const int* __restrict__ srcA, const int* __restrict__ trgA,
                    const int* __restrict__ srcB, const int* __restrict__ trgB,
                    int* __restrict__ cur, int* __restrict__ csr)
{
    int i = blockIdx.x * blockDim.x + threadIdx.x;
    if (i >= 2 * N_EDGES) return;
    int layer = (i >= N_EDGES);
    int e = i - layer * N_EDGES;
    const int* trg = layer ? trgB : trgA;
    const int* src = layer ? srcB : srcA;
    int t = __ldg(trg + e);
    if (t >= NUSER) return;
    int pos = atomicAdd(cur + layer * NUSER + t, 1);
    csr[pos] = __ldg(src + e);
}

// ---------------- gather: warp per (layer, target), unrolled x2 (R11) -------
__global__ __launch_bounds__(256)
void gather_kernel(const int* __restrict__ csr, const int* __restrict__ off,
                   const int* __restrict__ cnt,
                   const float* __restrict__ as_, const float* __restrict__ at_,
                   const __half* __restrict__ hp0, const __half* __restrict__ hp1,
                   float* __restrict__ ta)
{
    int w    = (blockIdx.x * blockDim.x + threadIdx.x) >> 5;
    int lane = threadIdx.x & 31;
    if (w >= NT2) return;
    int layer = (w >= NUSER);
    int t = w - layer * NUSER;
    const __half* hpL = layer ? hp1 : hp0;
    int abase = layer * N_NODES * 2;

    int grp  = lane >> 4;        // which edge of the pair
    int sub  = lane & 15;        // 16-lane slot within edge
    int hsel = sub >> 3;         // head of this lane

    float at_own = __ldg(at_ + abase + 2 * t + hsel);
    int start = __ldg(off + w);
    int n     = __ldg(cnt + w);

    float acc[8];
    #pragma unroll
    for (int j = 0; j < 8; j++) acc[j] = 0.f;
    float den = 0.f;

    int i = 0;
    for (; i + 4 <= n; i += 4) {
        int sA = __ldg(csr + start + i + grp);
        int sB = __ldg(csr + start + i + 2 + grp);
        float eA = __ldg(as_ + abase + 2 * sA + hsel) + at_own;
        float eB = __ldg(as_ + abase + 2 * sB + hsel) + at_own;
        eA = (eA > 0.f) ? eA : 0.2f * eA;
        eB = (eB > 0.f) ? eB : 0.2f * eB;
        float wA = __expf(eA);
        float wB = __expf(eB);
        uint4 rA = *(const uint4*)(hpL + (size_t)sA * 128 + sub * 8);
        uint4 rB = *(const uint4*)(hpL + (size_t)sB * 128 + sub * 8);
        den += wA + wB;
        float2 f;
        f = __half22float2(*reinterpret_cast<__half2*>(&rA.x));
        acc[0] = fmaf(wA, f.x, acc[0]); acc[1] = fmaf(wA, f.y, acc[1]);
        f = __half22float2(*reinterpret_cast<__half2*>(&rA.y));
        acc[2] = fmaf(wA, f.x, acc[2]); acc[3] = fmaf(wA, f.y, acc[3]);
        f = __half22float2(*reinterpret_cast<__half2*>(&rA.z));
        acc[4] = fmaf(wA, f.x, acc[4]); acc[5] = fmaf(wA, f.y, acc[5]);
        f = __half22float2(*reinterpret_cast<__half2*>(&rA.w));
        acc[6] = fmaf(wA, f.x, acc[6]); acc[7] = fmaf(wA, f.y, acc[7]);
        f = __half22float2(*reinterpret_cast<__half2*>(&rB.x));
        acc[0] = fmaf(wB, f.x, acc[0]); acc[1] = fmaf(wB, f.y, acc[1]);
        f = __half22float2(*reinterpret_cast<__half2*>(&rB.y));
        acc[2] = fmaf(wB, f.x, acc[2]); acc[3] = fmaf(wB, f.y, acc[3]);
        f = __half22float2(*reinterpret_cast<__half2*>(&rB.z));
        acc[4] = fmaf(wB, f.x, acc[4]); acc[5] = fmaf(wB, f.y, acc[5]);
        f = __half22float2(*reinterpret_cast<__half2*>(&rB.w));
        acc[6] = fmaf(wB, f.x, acc[6]); acc[7] = fmaf(wB, f.y, acc[7]);
    }
    for (; i < n; i += 2) {
        int idx = i + grp;
        bool valid = idx < n;
        int sidx = valid ? idx : i;
        int s = __ldg(csr + start + sidx);
        float e = __ldg(as_ + abase + 2 * s + hsel) + at_own;
        e = (e > 0.f) ? e : 0.2f * e;
        float wgt = valid ? __expf(e) : 0.f;
        den += wgt;
        uint4 r = *(const uint4*)(hpL + (size_t)s * 128 + sub * 8);
        float2 f;
        f = __half22float2(*reinterpret_cast<__half2*>(&r.x));
        acc[0] = fmaf(wgt, f.x, acc[0]); acc[1] = fmaf(wgt, f.y, acc[1]);
        f = __half22float2(*reinterpret_cast<__half2*>(&r.y));
        acc[2] = fmaf(wgt, f.x, acc[2]); acc[3] = fmaf(wgt, f.y, acc[3]);
        f = __half22float2(*reinterpret_cast<__half2*>(&r.z));
        acc[4] = fmaf(wgt, f.x, acc[4]); acc[5] = fmaf(wgt, f.y, acc[5]);
        f = __half22float2(*reinterpret_cast<__half2*>(&r.w));
        acc[6] = fmaf(wgt, f.x, acc[6]); acc[7] = fmaf(wgt, f.y, acc[7]);
    }

    den += __shfl_xor_sync(0xffffffffu, den, 16);
    #pragma unroll
    for (int j = 0; j < 8; j++)
        acc[j] += __shfl_xor_sync(0xffffffffu, acc[j], 16);

    float inv = 1.f / (den + 1e-16f);
    #pragma unroll
    for (int j = 0; j < 8; j++) acc[j] *= inv;

    float other[8];
    #pragma unroll
    for (int j = 0; j < 8; j++)
        other[j] = __shfl_xor_sync(0xffffffffu, acc[j], 8);

    if (grp == 0 && hsel == 0) {
        float4 r0 = make_float4(0.5f * (acc[0] + other[0]), 0.5f * (acc[1] + other[1]),
                                0.5f * (acc[2] + other[2]), 0.5f * (acc[3] + other[3]));
        float4 r1 = make_float4(0.5f * (acc[4] + other[4]), 0.5f * (acc[5] + other[5]),
                                0.5f * (acc[6] + other[6]), 0.5f * (acc[7] + other[7]));
        float* dst = ta + (size_t)t * 128 + layer * 64 + sub * 8;
        *(float4*)(dst)     = r0;
        *(float4*)(dst + 4) = r1;
    }
}

// ---------------- head: tanh-attention fusion + FC + log_softmax ------------
__global__ __launch_bounds__(256)
void head_kernel(const float* __restrict__ u, const float* __restrict__ v,
                 const float* __restrict__ ta,
                 const float* __restrict__ aam, const float* __restrict__ fcw,
                 const float* __restrict__ fcb, float* __restrict__ outp)
{
    int w    = (blockIdx.x * blockDim.x + threadIdx.x) >> 5;
    int lane = threadIdx.x & 31;
    if (w >= NUSER) return;
    int d1 = lane, d2 = lane + 32;

    float u1   = u[w * 64 + d1],            u2   = u[w * 64 + d2];
    float v01  = v[(2*w) * 64 + d1],        v02  = v[(2*w) * 64 + d2];
    float v11  = v[(2*w+1) * 64 + d1],      v12  = v[(2*w+1) * 64 + d2];
    float ta01 = ta[w * 128 + d1],          ta02 = ta[w * 128 + d2];
    float ta11 = ta[w * 128 + 64 + d1],     ta12 = ta[w * 128 + 64 + d2];
    float am1  = __ldg(aam + d1),           am2  = __ldg(aam + d2);

    float s0 = tanhf(u1 + v01) * am1 + tanhf(u2 + v02) * am2;
    float s1 = tanhf(u1 + v11) * am1 + tanhf(u2 + v12) * am2;
    #pragma unroll
    for (int o = 16; o > 0; o >>= 1) {
        s0 += __shfl_xor_sync(0xffffffffu, s0, o);
        s1 += __shfl_xor_sync(0xffffffffu, s1, o);
    }
    float m  = fmaxf(s0, s1);
    float e0 = expf(s0 - m), e1 = expf(s1 - m);
    float rb = 1.f / (e0 + e1);
    float b0 = e0 * rb, b1 = e1 * rb;

    float f1 = b0 * ta01 + b1 * ta11;
    float f2 = b0 * ta02 + b1 * ta12;

    float l0 = ta01 * __ldg(fcw + d1)        + ta02 * __ldg(fcw + d2)
             + ta11 * __ldg(fcw + 64 + d1)   + ta12 * __ldg(fcw + 64 + d2)
             + f1   * __ldg(fcw + 128 + d1)  + f2   * __ldg(fcw + 128 + d2);
    float l1 = ta01 * __ldg(fcw + 192 + d1)  + ta02 * __ldg(fcw + 192 + d2)
             + ta11 * __ldg(fcw + 256 + d1)  + ta12 * __ldg(fcw + 256 + d2)
             + f1   * __ldg(fcw + 320 + d1)  + f2   * __ldg(fcw + 320 + d2);
    #pragma unroll
    for (int o = 16; o > 0; o >>= 1) {
        l0 += __shfl_xor_sync(0xffffffffu, l0, o);
        l1 += __shfl_xor_sync(0xffffffffu, l1, o);
    }
    if (lane == 0) {
        l0 += __ldg(fcb + 0);
        l1 += __ldg(fcb + 1);
        float mm  = fmaxf(l0, l1);
        float lse = mm + logf(expf(l0 - mm) + expf(l1 - mm));
        outp[w * 2]     = l0 - lse;
        outp[w * 2 + 1] = l1 - lse;
    }
}

// ---------------- launch ----------------------------------------------------
extern "C" void kernel_launch(void* const* d_in, const int* in_sizes, int n_in,
                              void* d_out, int out_size)
{
    const float* h     = (const float*)d_in[0];
    const int*   src0  = (const int*)  d_in[1];
    const int*   trg0  = (const int*)  d_in[2];
    const int*   src1  = (const int*)  d_in[3];
    const int*   trg1  = (const int*)  d_in[4];
    const float* w0    = (const float*)d_in[5];
    const float* asrc0 = (const float*)d_in[6];
    const float* atrg0 = (const float*)d_in[7];
    const float* w1    = (const float*)d_in[8];
    const float* asrc1 = (const float*)d_in[9];
    const float* atrg1 = (const float*)d_in[10];
    const float* aaw1  = (const float*)d_in[11];
    const float* aaw2  = (const float*)d_in[12];
    const float* aam   = (const float*)d_in[13];
    const float* fcw   = (const float*)d_in[14];
    const float* fcb   = (const float*)d_in[15];
    float* out = (float*)d_out;

    __half *hp0, *hp1;
    float *as_, *at_, *ta, *u, *v;
    int *cnt, *off, *cur, *part, *csr;
    cudaGetSymbolAddress((void**)&hp0,  g_hp0);
    cudaGetSymbolAddress((void**)&hp1,  g_hp1);
    cudaGetSymbolAddress((void**)&as_,  g_as);
    cudaGetSymbolAddress((void**)&at_,  g_at);
    cudaGetSymbolAddress((void**)&ta,   g_ta);
    cudaGetSymbolAddress((void**)&u,    g_u);
    cudaGetSymbolAddress((void**)&v,    g_v);
    cudaGetSymbolAddress((void**)&cnt,  g_cnt);
    cudaGetSymbolAddress((void**)&off,  g_off);
    cudaGetSymbolAddress((void**)&cur,  g_cur);
    cudaGetSymbolAddress((void**)&part, g_part);
    cudaGetSymbolAddress((void**)&csr,  g_csr);

    cudaFuncSetAttribute(gemm_hp_fused, cudaFuncAttributeMaxDynamicSharedMemorySize, SM_HP);
    cudaFuncSetAttribute(gemm_head,     cudaFuncAttributeMaxDynamicSharedMemorySize, SM_HD);

    const int EDGE2_BLK = (2 * N_EDGES + 255) / 256;
    const int GATH_BLK  = (NT2 * 32 + 255) / 256;
    const int HEAD_BLK  = NUSER * 32 / 256;

    // CSR build for both layers
    zero_cnt_kernel<<<(NT2 + 255) / 256, 256>>>(cnt);
    hist_kernel<<<EDGE2_BLK, 256>>>(trg0, trg1, cnt);
    scan1_kernel<<<NPART, 256>>>(cnt, off, part);
    scan2_kernel<<<1, 256>>>(part);
    scan3_kernel<<<(NT2 + 255) / 256, 256>>>(off, part, cur);
    scatter_kernel<<<EDGE2_BLK, 256>>>(src0, trg0, src1, trg1, cur, csr);

    // hp GEMMs (both layers, tf32 tensor core) with fused attention logits
    dim3 ggrid((N_NODES + 127) / 128, 2);
    gemm_hp_fused<<<ggrid, 256, SM_HP>>>(h, w0, w1, asrc0, atrg0, asrc1, atrg1,
                                         hp0, hp1, as_, at_, N_NODES);

    // gather both layers
    gather_kernel<<<GATH_BLK, 256>>>(csr, off, cnt, as_, at_, hp0, hp1, ta);

    // head GEMMs (merged, tf32 tensor core) + head
    dim3 hgrid((NUSER * 2 + 127) / 128, 2);
    gemm_head<<<hgrid, 256, SM_HD>>>(h, aaw1, u, NUSER, ta, aaw2, v, NUSER * 2);
    head_kernel<<<HEAD_BLK, 256>>>(u, v, ta, aam, fcw, fcb, out);

    (void)in_sizes; (void)n_in; (void)out_size;
}

// round 16
// speedup vs baseline: 1.8819x; 1.0141x over previous
#include <cuda_runtime.h>
#include <cuda_fp16.h>
#include <math.h>

#define N_NODES 100000
#define N_EDGES 1600000
#define NUSER   90000
#define NT2     (2 * NUSER)            // merged bucket count = 180000
#define SCAN_CHUNK 1024
#define NPART   ((NT2 + SCAN_CHUNK - 1) / SCAN_CHUNK)   // 176

// ---------------- scratch (device globals; no allocation allowed) ----------
__device__ __align__(16) __half g_hp0[N_NODES * 128];
__device__ __align__(16) __half g_hp1[N_NODES * 128];
__device__ __align__(16) float g_as [2 * N_NODES * 2];  // [layer][n*2+h]
__device__ __align__(16) float g_at [2 * N_NODES * 2];
__device__ __align__(16) float g_ta [NUSER  * 128];     // type_aware (n, k, d)
__device__ __align__(16) float g_u  [NUSER  * 64];
__device__ __align__(16) float g_v  [NUSER  * 128];
__device__ __align__(16) int   g_cnt[NT2];              // counts
__device__ __align__(16) int   g_off[NT2];              // CSR offsets
__device__ __align__(16) int   g_cur[NT2];              // scatter cursors
__device__ __align__(16) int   g_part[256];
__device__ __align__(16) int   g_csr[2 * N_EDGES];      // bucketed src ids

// ---------------- tf32 helpers ----------------------------------------------
__device__ __forceinline__ unsigned f2tf32(float f)
{
    unsigned u;
    asm("cvt.rna.tf32.f32 %0, %1;" : "=r"(u) : "f"(f));
    return u;
}

__device__ __forceinline__ void mma_tf32(float d[4],
                                         unsigned a0, unsigned a1,
                                         unsigned a2, unsigned a3,
                                         unsigned b0, unsigned b1)
{
    asm volatile(
        "mma.sync.aligned.m16n8k8.row.col.f32.tf32.tf32.f32 "
        "{%0,%1,%2,%3}, {%4,%5,%6,%7}, {%8,%9}, {%0,%1,%2,%3};"
        : "+f"(d[0]), "+f"(d[1]), "+f"(d[2]), "+f"(d[3])
        : "r"(a0), "r"(a1), "r"(a2), "r"(a3), "r"(b0), "r"(b1));
}

// ---------------- fused hp GEMM (tf32 tensor core) + attn logits -------------
#define LDA_T 68
#define LDB_T 136
#define SM_HP ((128 * LDA_T + 64 * LDB_T + 2 * 4 * 128) * 4)   // 73728 B

__global__ __launch_bounds__(256)
void gemm_hp_fused(const float* __restrict__ A,
                   const float* __restrict__ W0, const float* __restrict__ W1,
                   const float* __restrict__ asrc0, const float* __restrict__ atrg0,
                   const float* __restrict__ asrc1, const float* __restrict__ atrg1,
                   __half* __restrict__ hp0, __half* __restrict__ hp1,
                   float* __restrict__ asOut, float* __restrict__ atOut, int M)
{
    const int layer = blockIdx.y;
    const float* Braw = layer ? W1 : W0;
    const float* aS   = layer ? asrc1 : asrc0;
    const float* aT   = layer ? atrg1 : atrg0;
    __half* hpL = layer ? hp1 : hp0;

    extern __shared__ float smem[];
    float* As  = smem;                          // [128][68]
    float* Bs  = smem + 128 * LDA_T;            // [64][136]
    float* pas = smem + 128 * LDA_T + 64 * LDB_T;   // [4][128]
    float* pat = pas + 4 * 128;                 // [4][128]

    const int t    = threadIdx.x;
    const int row0 = blockIdx.x * 128;

    #pragma unroll 4
    for (int i = t; i < 64 * 128; i += 256) {
        int kk = i >> 7, c = i & 127;
        Bs[kk * LDB_T + c] = Braw[(c >> 6) * 4096 + kk * 64 + (c & 63)];
    }
    #pragma unroll 4
    for (int i = t; i < 128 * 16; i += 256) {
        int r  = i >> 4;
        int k4 = (i & 15) << 2;
        float4 a = make_float4(0.f, 0.f, 0.f, 0.f);
        if (row0 + r < M) a = *(const float4*)(A + (size_t)(row0 + r) * 64 + k4);
        *(float4*)(As + r * LDA_T + k4) = a;
    }
    __syncthreads();

    const int wid   = t >> 5;
    const int lane  = t & 31;
    const int warpM = wid >> 2;
    const int warpN = wid & 3;
    const int g     = lane >> 2;
    const int tg    = lane & 3;
    const int m0    = warpM * 64;
    const int n0    = warpN * 32;

    float acc[4][4][4];
    #pragma unroll
    for (int m = 0; m < 4; m++)
        #pragma unroll
        for (int n = 0; n < 4; n++)
            #pragma unroll
            for (int j = 0; j < 4; j++) acc[m][n][j] = 0.f;

    #pragma unroll
    for (int ks = 0; ks < 8; ks++) {
        int k0 = ks * 8;
        unsigned areg[4][4];
        #pragma unroll
        for (int m = 0; m < 4; m++) {
            const float* Ap = As + (m0 + m * 16) * LDA_T + k0;
            areg[m][0] = f2tf32(Ap[g * LDA_T + tg]);
            areg[m][1] = f2tf32(Ap[(g + 8) * LDA_T + tg]);
            areg[m][2] = f2tf32(Ap[g * LDA_T + tg + 4]);
            areg[m][3] = f2tf32(Ap[(g + 8) * LDA_T + tg + 4]);
        }
        unsigned breg[4][2];
        #pragma unroll
        for (int n = 0; n < 4; n++) {
            const float* Bp = Bs + k0 * LDB_T + n0 + n * 8;
            breg[n][0] = f2tf32(Bp[tg * LDB_T + g]);
            breg[n][1] = f2tf32(Bp[(tg + 4) * LDB_T + g]);
        }
        #pragma unroll
        for (int m = 0; m < 4; m++)
            #pragma unroll
            for (int n = 0; n < 4; n++)
                mma_tf32(acc[m][n], areg[m][0], areg[m][1], areg[m][2], areg[m][3],
                         breg[n][0], breg[n][1]);
    }

    #pragma unroll
    for (int m = 0; m < 4; m++) {
        int r1 = row0 + m0 + m * 16 + g;
        int r2 = r1 + 8;
        #pragma unroll
        for (int n = 0; n < 4; n++) {
            int col = n0 + n * 8 + 2 * tg;
            if (r1 < M) {
                __half2 h2 = __floats2half2_rn(acc[m][n][0], acc[m][n][1]);
                *(unsigned*)(hpL + (size_t)r1 * 128 + col) = *(unsigned*)&h2;
            }
            if (r2 < M) {
                __half2 h2 = __floats2half2_rn(acc[m][n][2], acc[m][n][3]);
                *(unsigned*)(hpL + (size_t)r2 * 128 + col) = *(unsigned*)&h2;
            }
        }
    }

    float2 sv2[4], tv2[4];
    #pragma unroll
    for (int n = 0; n < 4; n++) {
        int col = n0 + n * 8 + 2 * tg;
        sv2[n] = make_float2(aS[col], aS[col + 1]);
        tv2[n] = make_float2(aT[col], aT[col + 1]);
    }
    #pragma unroll
    for (int m = 0; m < 4; m++) {
        float pa0 = 0.f, pa1 = 0.f, pt0 = 0.f, pt1 = 0.f;
        #pragma unroll
        for (int n = 0; n < 4; n++) {
            pa0 = fmaf(acc[m][n][0], sv2[n].x, fmaf(acc[m][n][1], sv2[n].y, pa0));
            pa1 = fmaf(acc[m][n][2], sv2[n].x, fmaf(acc[m][n][3], sv2[n].y, pa1));
            pt0 = fmaf(acc[m][n][0], tv2[n].x, fmaf(acc[m][n][1], tv2[n].y, pt0));
            pt1 = fmaf(acc[m][n][2], tv2[n].x, fmaf(acc[m][n][3], tv2[n].y, pt1));
        }
        #pragma unroll
        for (int o = 1; o < 4; o <<= 1) {
            pa0 += __shfl_xor_sync(0xffffffffu, pa0, o);
            pa1 += __shfl_xor_sync(0xffffffffu, pa1, o);
            pt0 += __shfl_xor_sync(0xffffffffu, pt0, o);
            pt1 += __shfl_xor_sync(0xffffffffu, pt1, o);
        }
        if (tg == 0) {
            int r = m0 + m * 16 + g;
            pas[warpN * 128 + r]     = pa0;
            pas[warpN * 128 + r + 8] = pa1;
            pat[warpN * 128 + r]     = pt0;
            pat[warpN * 128 + r + 8] = pt1;
        }
    }
    __syncthreads();

    if (t < 128) {
        int row = row0 + t;
        if (row < M) {
            int abase = layer * N_NODES * 2;
            asOut[abase + row * 2 + 0] = pas[t]       + pas[128 + t];
            asOut[abase + row * 2 + 1] = pas[256 + t] + pas[384 + t];
            atOut[abase + row * 2 + 0] = pat[t]       + pat[128 + t];
            atOut[abase + row * 2 + 1] = pat[256 + t] + pat[384 + t];
        }
    }
}

// ---------------- head GEMMs (tf32): C[Mx64] = A[Mx64] @ Braw^T --------------
#define LDB_H 72
#define SM_HD ((128 * LDA_T + 64 * LDB_H) * 4)   // 53248 B

__global__ __launch_bounds__(256)
void gemm_head(const float* __restrict__ A0, const float* __restrict__ B0,
               float* __restrict__ C0, int M0,
               const float* __restrict__ A1, const float* __restrict__ B1,
               float* __restrict__ C1, int M1)
{
    const int sel = blockIdx.y;
    const float* A    = sel ? A1 : A0;
    const float* Braw = sel ? B1 : B0;
    float*       C    = sel ? C1 : C0;
    const int    M    = sel ? M1 : M0;

    const int row0 = blockIdx.x * 128;
    if (row0 >= M) return;

    extern __shared__ float smem[];
    float* As = smem;                 // [128][68]
    float* Bs = smem + 128 * LDA_T;   // [64][72]

    const int t = threadIdx.x;

    #pragma unroll 4
    for (int i = t; i < 64 * 64; i += 256) {
        int kk = i >> 6, c = i & 63;
        Bs[kk * LDB_H + c] = Braw[c * 64 + kk];
    }
    #pragma unroll 4
    for (int i = t; i < 128 * 16; i += 256) {
        int r  = i >> 4;
        int k4 = (i & 15) << 2;
        float4 a = make_float4(0.f, 0.f, 0.f, 0.f);
        if (row0 + r < M) a = *(const float4*)(A + (size_t)(row0 + r) * 64 + k4);
        *(float4*)(As + r * LDA_T + k4) = a;
    }
    __syncthreads();

    const int wid   = t >> 5;
    const int lane  = t & 31;
    const int warpM = wid >> 2;
    const int warpN = wid & 3;
    const int g     = lane >> 2;
    const int tg    = lane & 3;
    const int m0    = warpM * 64;
    const int n0    = warpN * 16;

    float acc[4][2][4];
    #pragma unroll
    for (int m = 0; m < 4; m++)
        #pragma unroll
        for (int n = 0; n < 2; n++)
            #pragma unroll
            for (int j = 0; j < 4; j++) acc[m][n][j] = 0.f;

    #pragma unroll
    for (int ks = 0; ks < 8; ks++) {
        int k0 = ks * 8;
        unsigned areg[4][4];
        #pragma unroll
        for (int m = 0; m < 4; m++) {
            const float* Ap = As + (m0 + m * 16) * LDA_T + k0;
            areg[m][0] = f2tf32(Ap[g * LDA_T + tg]);
            areg[m][1] = f2tf32(Ap[(g + 8) * LDA_T + tg]);
            areg[m][2] = f2tf32(Ap[g * LDA_T + tg + 4]);
            areg[m][3] = f2tf32(Ap[(g + 8) * LDA_T + tg + 4]);
        }
        unsigned breg[2][2];
        #pragma unroll
        for (int n = 0; n < 2; n++) {
            const float* Bp = Bs + k0 * LDB_H + n0 + n * 8;
            breg[n][0] = f2tf32(Bp[tg * LDB_H + g]);
            breg[n][1] = f2tf32(Bp[(tg + 4) * LDB_H + g]);
        }
        #pragma unroll
        for (int m = 0; m < 4; m++)
            #pragma unroll
            for (int n = 0; n < 2; n++)
                mma_tf32(acc[m][n], areg[m][0], areg[m][1], areg[m][2], areg[m][3],
                         breg[n][0], breg[n][1]);
    }

    #pragma unroll
    for (int m = 0; m < 4; m++) {
        int r1 = row0 + m0 + m * 16 + g;
        int r2 = r1 + 8;
        #pragma unroll
        for (int n = 0; n < 2; n++) {
            int col = n0 + n * 8 + 2 * tg;
            if (r1 < M) {
                float2 o = make_float2(acc[m][n][0], acc[m][n][1]);
                *(float2*)(C + (size_t)r1 * 64 + col) = o;
            }
            if (r2 < M) {
                float2 o = make_float2(acc[m][n][2], acc[m][n][3]);
                *(float2*)(C + (size_t)r2 * 64 + col) = o;
            }
        }
    }
}

// ---------------- CSR build --------------------------------------------------
__global__ void zero_cnt_kernel(int* __restrict__ cnt)
{
    int i = blockIdx.x * blockDim.x + threadIdx.x;
    if (i < NT2) cnt[i] = 0;
}

__global__ __launch_bounds__(256)
void hist_kernel(const int* __restrict__ trgA, const int* __restrict__ trgB,
                 int* __restrict__ cnt)
{
    int i = blockIdx.x * blockDim.x + threadIdx.x;
    if (i >= 2 * N_EDGES) return;
    int layer = (i >= N_EDGES);
    const int* trg = layer ? trgB : trgA;
    int t = __ldg(trg + (i - layer * N_EDGES));
    if (t < NUSER) atomicAdd(cnt + layer * NUSER + t, 1);
}

__global__ __launch_bounds__(256)
void scan1_kernel(const int* __restrict__ cnt, int* __restrict__ off,
                  int* __restrict__ part)
{
    __shared__ int s[256];
    int t = threadIdx.x, b = blockIdx.x;
    int i0 = b * SCAN_CHUNK + t * 4;
    int c[4];
    #pragma unroll
    for (int j = 0; j < 4; j++) c[j] = (i0 + j < NT2) ? cnt[i0 + j] : 0;
    int tot = c[0] + c[1] + c[2] + c[3];
    s[t] = tot;
    __syncthreads();
    int v = s[t];
    #pragma unroll
    for (int o = 1; o < 256; o <<= 1) {
        int u = (t >= o) ? s[t - o] : 0;
        __syncthreads();
        v += u; s[t] = v;
        __syncthreads();
    }
    int excl = v - tot;
    #pragma unroll
    for (int j = 0; j < 4; j++) {
        if (i0 + j < NT2) off[i0 + j] = excl;
        excl += c[j];
    }
    if (t == 255) part[b] = v;
}

__global__ void scan2_kernel(int* __restrict__ part)
{
    __shared__ int s[256];
    int t = threadIdx.x;
    int own = (t < NPART) ? part[t] : 0;
    s[t] = own;
    __syncthreads();
    int v = s[t];
    #pragma unroll
    for (int o = 1; o < 256; o <<= 1) {
        int u = (t >= o) ? s[t - o] : 0;
        __syncthreads();
        v += u; s[t] = v;
        __syncthreads();
    }
    if (t < NPART) part[t] = v - own;
}

// add chunk base AND initialize scatter cursor
__global__ void scan3_kernel(int* __restrict__ off, const int* __restrict__ part,
                             int* __restrict__ cur)
{
    int i = blockIdx.x * blockDim.x + threadIdx.x;
    if (i < NT2) {
        int o = off[i] + part[i / SCAN_CHUNK];
        off[i] = o;
        cur[i] = o;
    }
}

__global__ __launch_bounds__(256)
void scatter_kernel(const int* __restrict__ srcA, const int* __restrict__ trgA,
                    const int* __restrict__ srcB, const int* __restrict__ trgB,
                    int* __restrict__ cur, int* __restrict__ csr)
{
    int i = blockIdx.x * blockDim.x + threadIdx.x;
    if (i >= 2 * N_EDGES) return;
    int layer = (i >= N_EDGES);
    int e = i - layer * N_EDGES;
    const int* trg = layer ? trgB : trgA;
    const int* src = layer ? srcB : srcA;
    int t = __ldg(trg + e);
    if (t >= NUSER) return;
    int pos = atomicAdd(cur + layer * NUSER + t, 1);
    csr[pos] = __ldg(src + e);
}

// ---------------- gather: warp per (layer, target), unrolled x2 (R11) -------
__global__ __launch_bounds__(256)
void gather_kernel(const int* __restrict__ csr, const int* __restrict__ off,
                   const int* __restrict__ cnt,
                   const float* __restrict__ as_, const float* __restrict__ at_,
                   const __half* __restrict__ hp0, const __half* __restrict__ hp1,
                   float* __restrict__ ta)
{
    int w    = (blockIdx.x * blockDim.x + threadIdx.x) >> 5;
    int lane = threadIdx.x & 31;
    if (w >= NT2) return;
    int layer = (w >= NUSER);
    int t = w - layer * NUSER;
    const __half* hpL = layer ? hp1 : hp0;
    int abase = layer * N_NODES * 2;

    int grp  = lane >> 4;        // which edge of the pair
    int sub  = lane & 15;        // 16-lane slot within edge
    int hsel = sub >> 3;         // head of this lane

    float at_own = __ldg(at_ + abase + 2 * t + hsel);
    int start = __ldg(off + w);
    int n     = __ldg(cnt + w);

    float acc[8];
    #pragma unroll
    for (int j = 0; j < 8; j++) acc[j] = 0.f;
    float den = 0.f;

    int i = 0;
    for (; i + 4 <= n; i += 4) {
        int sA = __ldg(csr + start + i + grp);
        int sB = __ldg(csr + start + i + 2 + grp);
        float eA = __ldg(as_ + abase + 2 * sA + hsel) + at_own;
        float eB = __ldg(as_ + abase + 2 * sB + hsel) + at_own;
        eA = (eA > 0.f) ? eA : 0.2f * eA;
        eB = (eB > 0.f) ? eB : 0.2f * eB;
        float wA = __expf(eA);
        float wB = __expf(eB);
        uint4 rA = *(const uint4*)(hpL + (size_t)sA * 128 + sub * 8);
        uint4 rB = *(const uint4*)(hpL + (size_t)sB * 128 + sub * 8);
        den += wA + wB;
        float2 f;
        f = __half22float2(*reinterpret_cast<__half2*>(&rA.x));
        acc[0] = fmaf(wA, f.x, acc[0]); acc[1] = fmaf(wA, f.y, acc[1]);
        f = __half22float2(*reinterpret_cast<__half2*>(&rA.y));
        acc[2] = fmaf(wA, f.x, acc[2]); acc[3] = fmaf(wA, f.y, acc[3]);
        f = __half22float2(*reinterpret_cast<__half2*>(&rA.z));
        acc[4] = fmaf(wA, f.x, acc[4]); acc[5] = fmaf(wA, f.y, acc[5]);
        f = __half22float2(*reinterpret_cast<__half2*>(&rA.w));
        acc[6] = fmaf(wA, f.x, acc[6]); acc[7] = fmaf(wA, f.y, acc[7]);
        f = __half22float2(*reinterpret_cast<__half2*>(&rB.x));
        acc[0] = fmaf(wB, f.x, acc[0]); acc[1] = fmaf(wB, f.y, acc[1]);
        f = __half22float2(*reinterpret_cast<__half2*>(&rB.y));
        acc[2] = fmaf(wB, f.x, acc[2]); acc[3] = fmaf(wB, f.y, acc[3]);
        f = __half22float2(*reinterpret_cast<__half2*>(&rB.z));
        acc[4] = fmaf(wB, f.x, acc[4]); acc[5] = fmaf(wB, f.y, acc[5]);
        f = __half22float2(*reinterpret_cast<__half2*>(&rB.w));
        acc[6] = fmaf(wB, f.x, acc[6]); acc[7] = fmaf(wB, f.y, acc[7]);
    }
    for (; i < n; i += 2) {
        int idx = i + grp;
        bool valid = idx < n;
        int sidx = valid ? idx : i;
        int s = __ldg(csr + start + sidx);
        float e = __ldg(as_ + abase + 2 * s + hsel) + at_own;
        e = (e > 0.f) ? e : 0.2f * e;
        float wgt = valid ? __expf(e) : 0.f;
        den += wgt;
        uint4 r = *(const uint4*)(hpL + (size_t)s * 128 + sub * 8);
        float2 f;
        f = __half22float2(*reinterpret_cast<__half2*>(&r.x));
        acc[0] = fmaf(wgt, f.x, acc[0]); acc[1] = fmaf(wgt, f.y, acc[1]);
        f = __half22float2(*reinterpret_cast<__half2*>(&r.y));
        acc[2] = fmaf(wgt, f.x, acc[2]); acc[3] = fmaf(wgt, f.y, acc[3]);
        f = __half22float2(*reinterpret_cast<__half2*>(&r.z));
        acc[4] = fmaf(wgt, f.x, acc[4]); acc[5] = fmaf(wgt, f.y, acc[5]);
        f = __half22float2(*reinterpret_cast<__half2*>(&r.w));
        acc[6] = fmaf(wgt, f.x, acc[6]); acc[7] = fmaf(wgt, f.y, acc[7]);
    }

    den += __shfl_xor_sync(0xffffffffu, den, 16);
    #pragma unroll
    for (int j = 0; j < 8; j++)
        acc[j] += __shfl_xor_sync(0xffffffffu, acc[j], 16);

    float inv = 1.f / (den + 1e-16f);
    #pragma unroll
    for (int j = 0; j < 8; j++) acc[j] *= inv;

    float other[8];
    #pragma unroll
    for (int j = 0; j < 8; j++)
        other[j] = __shfl_xor_sync(0xffffffffu, acc[j], 8);

    if (grp == 0 && hsel == 0) {
        float4 r0 = make_float4(0.5f * (acc[0] + other[0]), 0.5f * (acc[1] + other[1]),
                                0.5f * (acc[2] + other[2]), 0.5f * (acc[3] + other[3]));
        float4 r1 = make_float4(0.5f * (acc[4] + other[4]), 0.5f * (acc[5] + other[5]),
                                0.5f * (acc[6] + other[6]), 0.5f * (acc[7] + other[7]));
        float* dst = ta + (size_t)t * 128 + layer * 64 + sub * 8;
        *(float4*)(dst)     = r0;
        *(float4*)(dst + 4) = r1;
    }
}

// ---------------- head: tanh-attention fusion + FC + log_softmax ------------
__global__ __launch_bounds__(256)
void head_kernel(const float* __restrict__ u, const float* __restrict__ v,
                 const float* __restrict__ ta,
                 const float* __restrict__ aam, const float* __restrict__ fcw,
                 const float* __restrict__ fcb, float* __restrict__ outp)
{
    int w    = (blockIdx.x * blockDim.x + threadIdx.x) >> 5;
    int lane = threadIdx.x & 31;
    if (w >= NUSER) return;
    int d1 = lane, d2 = lane + 32;

    float u1   = u[w * 64 + d1],            u2   = u[w * 64 + d2];
    float v01  = v[(2*w) * 64 + d1],        v02  = v[(2*w) * 64 + d2];
    float v11  = v[(2*w+1) * 64 + d1],      v12  = v[(2*w+1) * 64 + d2];
    float ta01 = ta[w * 128 + d1],          ta02 = ta[w * 128 + d2];
    float ta11 = ta[w * 128 + 64 + d1],     ta12 = ta[w * 128 + 64 + d2];
    float am1  = __ldg(aam + d1),           am2  = __ldg(aam + d2);

    float s0 = tanhf(u1 + v01) * am1 + tanhf(u2 + v02) * am2;
    float s1 = tanhf(u1 + v11) * am1 + tanhf(u2 + v12) * am2;
    #pragma unroll
    for (int o = 16; o > 0; o >>= 1) {
        s0 += __shfl_xor_sync(0xffffffffu, s0, o);
        s1 += __shfl_xor_sync(0xffffffffu, s1, o);
    }
    float m  = fmaxf(s0, s1);
    float e0 = expf(s0 - m), e1 = expf(s1 - m);
    float rb = 1.f / (e0 + e1);
    float b0 = e0 * rb, b1 = e1 * rb;

    float f1 = b0 * ta01 + b1 * ta11;
    float f2 = b0 * ta02 + b1 * ta12;

    float l0 = ta01 * __ldg(fcw + d1)        + ta02 * __ldg(fcw + d2)
             + ta11 * __ldg(fcw + 64 + d1)   + ta12 * __ldg(fcw + 64 + d2)
             + f1   * __ldg(fcw + 128 + d1)  + f2   * __ldg(fcw + 128 + d2);
    float l1 = ta01 * __ldg(fcw + 192 + d1)  + ta02 * __ldg(fcw + 192 + d2)
             + ta11 * __ldg(fcw + 256 + d1)  + ta12 * __ldg(fcw + 256 + d2)
             + f1   * __ldg(fcw + 320 + d1)  + f2   * __ldg(fcw + 320 + d2);
    #pragma unroll
    for (int o = 16; o > 0; o >>= 1) {
        l0 += __shfl_xor_sync(0xffffffffu, l0, o);
        l1 += __shfl_xor_sync(0xffffffffu, l1, o);
    }
    if (lane == 0) {
        l0 += __ldg(fcb + 0);
        l1 += __ldg(fcb + 1);
        float mm  = fmaxf(l0, l1);
        float lse = mm + logf(expf(l0 - mm) + expf(l1 - mm));
        outp[w * 2]     = l0 - lse;
        outp[w * 2 + 1] = l1 - lse;
    }
}

// ---------------- launch ----------------------------------------------------
extern "C" void kernel_launch(void* const* d_in, const int* in_sizes, int n_in,
                              void* d_out, int out_size)
{
    const float* h     = (const float*)d_in[0];
    const int*   src0  = (const int*)  d_in[1];
    const int*   trg0  = (const int*)  d_in[2];
    const int*   src1  = (const int*)  d_in[3];
    const int*   trg1  = (const int*)  d_in[4];
    const float* w0    = (const float*)d_in[5];
    const float* asrc0 = (const float*)d_in[6];
    const float* atrg0 = (const float*)d_in[7];
    const float* w1    = (const float*)d_in[8];
    const float* asrc1 = (const float*)d_in[9];
    const float* atrg1 = (const float*)d_in[10];
    const float* aaw1  = (const float*)d_in[11];
    const float* aaw2  = (const float*)d_in[12];
    const float* aam   = (const float*)d_in[13];
    const float* fcw   = (const float*)d_in[14];
    const float* fcb   = (const float*)d_in[15];
    float* out = (float*)d_out;

    __half *hp0, *hp1;
    float *as_, *at_, *ta, *u, *v;
    int *cnt, *off, *cur, *part, *csr;
    cudaGetSymbolAddress((void**)&hp0,  g_hp0);
    cudaGetSymbolAddress((void**)&hp1,  g_hp1);
    cudaGetSymbolAddress((void**)&as_,  g_as);
    cudaGetSymbolAddress((void**)&at_,  g_at);
    cudaGetSymbolAddress((void**)&ta,   g_ta);
    cudaGetSymbolAddress((void**)&u,    g_u);
    cudaGetSymbolAddress((void**)&v,    g_v);
    cudaGetSymbolAddress((void**)&cnt,  g_cnt);
    cudaGetSymbolAddress((void**)&off,  g_off);
    cudaGetSymbolAddress((void**)&cur,  g_cur);
    cudaGetSymbolAddress((void**)&part, g_part);
    cudaGetSymbolAddress((void**)&csr,  g_csr);

    cudaFuncSetAttribute(gemm_hp_fused, cudaFuncAttributeMaxDynamicSharedMemorySize, SM_HP);
    cudaFuncSetAttribute(gemm_head,     cudaFuncAttributeMaxDynamicSharedMemorySize, SM_HD);

    // side stream + fork/join events, created once on the first (uncaptured)
    // correctness call; replay work is identical every call.
    static cudaStream_t s1 = 0;
    static cudaEvent_t  evFork = 0, evJoin = 0;
    if (!s1) {
        cudaStreamCreateWithFlags(&s1, cudaStreamNonBlocking);
        cudaEventCreateWithFlags(&evFork, cudaEventDisableTiming);
        cudaEventCreateWithFlags(&evJoin, cudaEventDisableTiming);
    }

    const int EDGE2_BLK = (2 * N_EDGES + 255) / 256;
    const int GATH_BLK  = (NT2 * 32 + 255) / 256;
    const int HEAD_BLK  = NUSER * 32 / 256;

    // ---- fork: CSR build chain on side stream -------------------------------
    cudaEventRecord(evFork, 0);
    cudaStreamWaitEvent(s1, evFork, 0);

    zero_cnt_kernel<<<(NT2 + 255) / 256, 256, 0, s1>>>(cnt);
    hist_kernel<<<EDGE2_BLK, 256, 0, s1>>>(trg0, trg1, cnt);
    scan1_kernel<<<NPART, 256, 0, s1>>>(cnt, off, part);
    scan2_kernel<<<1, 256, 0, s1>>>(part);
    scan3_kernel<<<(NT2 + 255) / 256, 256, 0, s1>>>(off, part, cur);
    scatter_kernel<<<EDGE2_BLK, 256, 0, s1>>>(src0, trg0, src1, trg1, cur, csr);
    cudaEventRecord(evJoin, s1);

    // ---- concurrent on default stream: hp GEMMs (tf32) ----------------------
    dim3 ggrid((N_NODES + 127) / 128, 2);
    gemm_hp_fused<<<ggrid, 256, SM_HP>>>(h, w0, w1, asrc0, atrg0, asrc1, atrg1,
                                         hp0, hp1, as_, at_, N_NODES);

    // ---- join, then gather + heads ------------------------------------------
    cudaStreamWaitEvent(0, evJoin, 0);
    gather_kernel<<<GATH_BLK, 256>>>(csr, off, cnt, as_, at_, hp0, hp1, ta);

    dim3 hgrid((NUSER * 2 + 127) / 128, 2);
    gemm_head<<<hgrid, 256, SM_HD>>>(h, aaw1, u, NUSER, ta, aaw2, v, NUSER * 2);
    head_kernel<<<HEAD_BLK, 256>>>(u, v, ta, aam, fcw, fcb, out);

    (void)in_sizes; (void)n_in; (void)out_size;
}